// round 4
// baseline (speedup 1.0000x reference)
#include <cuda_runtime.h>

#define B_   8
#define T_   1024
#define E_   512
#define H_   1024
#define NH_  4
#define QD_  256
#define VD_  512
#define C1_  512
#define C2_  2
#define BT_  (B_ * T_)
#define G4_  (4 * H_)

__device__ float g_h1[(size_t)BT_ * E_];
__device__ float g_hh[(size_t)BT_ * E_];
__device__ float g_q [(size_t)BT_ * (NH_ * QD_)];
__device__ float g_k [(size_t)BT_ * (NH_ * QD_)];
__device__ float g_v [(size_t)BT_ * (NH_ * VD_)];
__device__ float g_sc[(size_t)B_ * NH_ * T_ * T_];
__device__ float g_o [(size_t)BT_ * (NH_ * VD_)];
__device__ float g_y [(size_t)BT_ * E_];
__device__ float g_gx[(size_t)BT_ * G4_];
__device__ float g_lstm[(size_t)BT_ * H_];
__device__ float g_hbuf[2 * B_ * H_];
__device__ float g_a1[(size_t)B_ * C1_ * T_];
__device__ float g_a2[(size_t)B_ * C2_ * T_];
__device__ float g_wc1t[(size_t)3 * C1_ * H_];
__device__ unsigned g_bar;

// ---------- generic batched SGEMM: C = act(A @ op(B) + bias) ----------
template<int ACT, int TRANSB, int HASBIAS>
__global__ __launch_bounds__(256)
void gemm_kernel(const float* __restrict__ A, const float* __restrict__ Bm,
                 const float* __restrict__ bias, float* __restrict__ C,
                 int M, int N, int Kd, int lda, int ldb, int ldc,
                 int bInner, long sAo, long sAi, long sBo, long sBi,
                 long sCo, long sCi)
{
    int z  = blockIdx.z;
    int zo = z / bInner, zi = z % bInner;
    A  += zo * sAo + zi * sAi;
    Bm += zo * sBo + zi * sBi;
    C  += zo * sCo + zi * sCi;

    __shared__ float As[16][64];
    __shared__ float Bs[16][64];

    int tid = threadIdx.x;
    int tx = tid & 15, ty = tid >> 4;
    int m0 = blockIdx.y * 64, n0 = blockIdx.x * 64;
    int arow = tid >> 2, akq = (tid & 3) * 4;

    float acc[4][4];
#pragma unroll
    for (int i = 0; i < 4; i++)
#pragma unroll
        for (int j = 0; j < 4; j++) acc[i][j] = 0.f;

    for (int k0 = 0; k0 < Kd; k0 += 16) {
        {
            int m = m0 + arow;
            float4 v = make_float4(0.f, 0.f, 0.f, 0.f);
            if (m < M) v = *(const float4*)&A[(long)m * lda + k0 + akq];
            As[akq + 0][arow] = v.x; As[akq + 1][arow] = v.y;
            As[akq + 2][arow] = v.z; As[akq + 3][arow] = v.w;
        }
        if (TRANSB) {
            int n = n0 + arow;
            float4 v = make_float4(0.f, 0.f, 0.f, 0.f);
            if (n < N) v = *(const float4*)&Bm[(long)n * ldb + k0 + akq];
            Bs[akq + 0][arow] = v.x; Bs[akq + 1][arow] = v.y;
            Bs[akq + 2][arow] = v.z; Bs[akq + 3][arow] = v.w;
        } else {
#pragma unroll
            for (int p = 0; p < 4; p++) {
                int kk = (tid >> 6) + p * 4;
                int n  = n0 + (tid & 63);
                float v = 0.f;
                if (n < N) v = Bm[(long)(k0 + kk) * ldb + n];
                Bs[kk][tid & 63] = v;
            }
        }
        __syncthreads();
#pragma unroll
        for (int kk = 0; kk < 16; kk++) {
            float4 av = *(const float4*)&As[kk][ty * 4];
            float4 bv = *(const float4*)&Bs[kk][tx * 4];
            float a[4] = {av.x, av.y, av.z, av.w};
            float b[4] = {bv.x, bv.y, bv.z, bv.w};
#pragma unroll
            for (int i = 0; i < 4; i++)
#pragma unroll
                for (int j = 0; j < 4; j++) acc[i][j] += a[i] * b[j];
        }
        __syncthreads();
    }
#pragma unroll
    for (int i = 0; i < 4; i++) {
        int m = m0 + ty * 4 + i;
        if (m >= M) continue;
#pragma unroll
        for (int j = 0; j < 4; j++) {
            int n = n0 + tx * 4 + j;
            if (n >= N) continue;
            float v = acc[i][j];
            if (HASBIAS) v += bias[n];
            if (ACT == 1) v = v >= 0.f ? v : 0.25f * v;
            C[(long)m * ldc + n] = v;
        }
    }
}

// ---------- softmax over rows of 1024 (in place), 256 threads ----------
__global__ void softmax_kernel(float* __restrict__ data)
{
    long row = blockIdx.x;
    float4* p = (float4*)(data + row * 1024);
    float4 v = p[threadIdx.x];
    int lane = threadIdx.x & 31, w = threadIdx.x >> 5;
    __shared__ float sm[8], ss[8];

    float m = fmaxf(fmaxf(v.x, v.y), fmaxf(v.z, v.w));
#pragma unroll
    for (int o = 16; o; o >>= 1) m = fmaxf(m, __shfl_xor_sync(0xffffffffu, m, o));
    if (lane == 0) sm[w] = m;
    __syncthreads();
    float bm = sm[0];
#pragma unroll
    for (int i = 1; i < 8; i++) bm = fmaxf(bm, sm[i]);

    v.x = __expf(v.x - bm); v.y = __expf(v.y - bm);
    v.z = __expf(v.z - bm); v.w = __expf(v.w - bm);
    float s = v.x + v.y + v.z + v.w;
#pragma unroll
    for (int o = 16; o; o >>= 1) s += __shfl_xor_sync(0xffffffffu, s, o);
    if (lane == 0) ss[w] = s;
    __syncthreads();
    float bs = ss[0] + ss[1] + ss[2] + ss[3] + ss[4] + ss[5] + ss[6] + ss[7];
    float inv = 1.f / bs;
    v.x *= inv; v.y *= inv; v.z *= inv; v.w *= inv;
    p[threadIdx.x] = v;
}

// ---------- LayerNorm over E=512, 128 threads ----------
__global__ void layernorm_kernel(const float* __restrict__ x, const float* __restrict__ g,
                                 const float* __restrict__ bta, float* __restrict__ y)
{
    long row = blockIdx.x;
    const float4* xr = (const float4*)(x + row * 512);
    float4 v = xr[threadIdx.x];
    int lane = threadIdx.x & 31, w = threadIdx.x >> 5;
    float s1 = v.x + v.y + v.z + v.w;
    float s2 = v.x * v.x + v.y * v.y + v.z * v.z + v.w * v.w;
#pragma unroll
    for (int o = 16; o; o >>= 1) {
        s1 += __shfl_xor_sync(0xffffffffu, s1, o);
        s2 += __shfl_xor_sync(0xffffffffu, s2, o);
    }
    __shared__ float a1s[4], a2s[4];
    if (lane == 0) { a1s[w] = s1; a2s[w] = s2; }
    __syncthreads();
    s1 = a1s[0] + a1s[1] + a1s[2] + a1s[3];
    s2 = a2s[0] + a2s[1] + a2s[2] + a2s[3];
    float mean = s1 * (1.f / 512.f);
    float var  = s2 * (1.f / 512.f) - mean * mean;
    float inv  = rsqrtf(var + 1e-5f);
    float4 gv = ((const float4*)g)[threadIdx.x];
    float4 bv = ((const float4*)bta)[threadIdx.x];
    float4 o4;
    o4.x = (v.x - mean) * inv * gv.x + bv.x;
    o4.y = (v.y - mean) * inv * gv.y + bv.y;
    o4.z = (v.z - mean) * inv * gv.z + bv.z;
    o4.w = (v.w - mean) * inv * gv.w + bv.w;
    ((float4*)(y + row * 512))[threadIdx.x] = o4;
}

__global__ void reset_kernel()
{
    int i = blockIdx.x * blockDim.x + threadIdx.x;
    if (i < 2 * B_ * H_) g_hbuf[i] = 0.f;
    if (i == 0) g_bar = 0u;
}

__device__ __forceinline__ float2 ffma2(float2 a, float2 b, float2 c)
{
    unsigned long long A = *reinterpret_cast<unsigned long long*>(&a);
    unsigned long long Bb = *reinterpret_cast<unsigned long long*>(&b);
    unsigned long long Cc = *reinterpret_cast<unsigned long long*>(&c);
    unsigned long long D;
    asm("fma.rn.f32x2 %0, %1, %2, %3;" : "=l"(D) : "l"(A), "l"(Bb), "l"(Cc));
    return *reinterpret_cast<float2*>(&D);
}

#define LSTM_NB 128
__global__ __launch_bounds__(256, 1)
void lstm_kernel(const float* __restrict__ gx, const float* __restrict__ Whh,
                 const float* __restrict__ bhh, float* __restrict__ hbuf,
                 float* __restrict__ lstm_out)
{
    const int tid  = threadIdx.x;
    const int lane = tid & 31;
    const int w    = tid >> 5;
    const int bi   = blockIdx.x;

    __shared__ float sh[8][1024];
    __shared__ float sg[32][8];
    __shared__ float scs[8][8];

    // warp w owns local gate rows lr=w*4..w*4+3; lr -> gate gt=lr>>3, unit ul=lr&7
    // global row j = gt*H + bi*8 + ul; lane holds float2 cols (kk*32+lane)
    float2 wreg[4][16];
#pragma unroll
    for (int r = 0; r < 4; r++) {
        int lr = w * 4 + r;
        int j  = (lr >> 3) * H_ + bi * 8 + (lr & 7);
        const float2* wrow = (const float2*)(Whh + (long)j * H_);
#pragma unroll
        for (int kk = 0; kk < 16; kk++) wreg[r][kk] = wrow[kk * 32 + lane];
    }
    if (tid < 64) scs[tid >> 3][tid & 7] = 0.f;

    unsigned target = 0;
    for (int t = 0; t < T_; t++) {
        const float4* hr = (const float4*)(hbuf + (t & 1) * (B_ * H_));
        float*        hw =                 hbuf + ((t + 1) & 1) * (B_ * H_);
#pragma unroll
        for (int p = 0; p < 8; p++)
            ((float4*)&sh[0][0])[tid + p * 256] = hr[tid + p * 256];
        __syncthreads();

#pragma unroll
        for (int bh = 0; bh < 2; bh++) {
            float2 acc[4][4];
#pragma unroll
            for (int r = 0; r < 4; r++)
#pragma unroll
                for (int b = 0; b < 4; b++) acc[r][b] = make_float2(0.f, 0.f);
#pragma unroll
            for (int kk = 0; kk < 16; kk++) {
                float2 h2[4];
#pragma unroll
                for (int b = 0; b < 4; b++)
                    h2[b] = *(const float2*)&sh[bh * 4 + b][kk * 64 + lane * 2];
#pragma unroll
                for (int r = 0; r < 4; r++) {
                    float2 wv = wreg[r][kk];
#pragma unroll
                    for (int b = 0; b < 4; b++) acc[r][b] = ffma2(wv, h2[b], acc[r][b]);
                }
            }
#pragma unroll
            for (int r = 0; r < 4; r++)
#pragma unroll
                for (int b = 0; b < 4; b++) {
                    float s = acc[r][b].x + acc[r][b].y;
#pragma unroll
                    for (int o = 16; o; o >>= 1) s += __shfl_xor_sync(0xffffffffu, s, o);
                    if (lane == r * 4 + b) sg[w * 4 + r][bh * 4 + b] = s;
                }
        }
        __syncthreads();

        if (tid < 64) {
            int ul = tid >> 3, b = tid & 7;
            int u  = bi * 8 + ul;
            long grow = ((long)b * T_ + t) * G4_;
            float gi = sg[0 * 8 + ul][b] + gx[grow + 0 * H_ + u] + bhh[0 * H_ + u];
            float gf = sg[1 * 8 + ul][b] + gx[grow + 1 * H_ + u] + bhh[1 * H_ + u];
            float gg = sg[2 * 8 + ul][b] + gx[grow + 2 * H_ + u] + bhh[2 * H_ + u];
            float go = sg[3 * 8 + ul][b] + gx[grow + 3 * H_ + u] + bhh[3 * H_ + u];
            float i_ = 1.f / (1.f + __expf(-gi));
            float f_ = 1.f / (1.f + __expf(-gf));
            float o_ = 1.f / (1.f + __expf(-go));
            float c  = f_ * scs[ul][b] + i_ * tanhf(gg);
            float hn = o_ * tanhf(c);
            scs[ul][b] = c;
            hw[b * H_ + u] = hn;
            lstm_out[((long)b * T_ + t) * H_ + u] = hn;
            __threadfence();
        }
        __syncthreads();

        target += LSTM_NB;
        if (tid == 0) {
            atomicAdd(&g_bar, 1u);
            while (atomicAdd(&g_bar, 0u) < target) { __nanosleep(64); }
            __threadfence();
        }
        __syncthreads();
    }
}

// ---------- conv weight repack: w[c][h][dk] -> wt[dk][c][h] ----------
__global__ void repack_wc1(const float* __restrict__ w, float* __restrict__ wt)
{
    int idx = blockIdx.x * blockDim.x + threadIdx.x;
    if (idx < C1_ * H_ * 3) {
        int dk = idx % 3;
        int h  = (idx / 3) % H_;
        int c  = idx / (3 * H_);
        wt[(long)dk * C1_ * H_ + (long)c * H_ + h] = w[idx];
    }
}

// ---------- conv1: relu(conv(lstm_out)) -> [B,C1,T] ----------
__global__ __launch_bounds__(256)
void conv1_kernel(const float* __restrict__ X, const float* __restrict__ Wt,
                  const float* __restrict__ bias, float* __restrict__ Y)
{
    int b  = blockIdx.z;
    int t0 = blockIdx.y * 64, c0 = blockIdx.x * 64;
    __shared__ float As[16][64];
    __shared__ float Bs[16][64];
    int tid = threadIdx.x;
    int tx = tid & 15, ty = tid >> 4;
    int arow = tid >> 2, akq = (tid & 3) * 4;

    float acc[4][4];
#pragma unroll
    for (int i = 0; i < 4; i++)
#pragma unroll
        for (int j = 0; j < 4; j++) acc[i][j] = 0.f;

    for (int dk = 0; dk < 3; dk++) {
        const float* Wd = Wt + (long)dk * C1_ * H_;
        for (int k0 = 0; k0 < H_; k0 += 16) {
            int t = t0 + arow + dk - 1;
            float4 v = make_float4(0.f, 0.f, 0.f, 0.f);
            if (t >= 0 && t < T_)
                v = *(const float4*)&X[((long)b * T_ + t) * H_ + k0 + akq];
            As[akq + 0][arow] = v.x; As[akq + 1][arow] = v.y;
            As[akq + 2][arow] = v.z; As[akq + 3][arow] = v.w;
            float4 wv = *(const float4*)&Wd[(long)(c0 + arow) * H_ + k0 + akq];
            Bs[akq + 0][arow] = wv.x; Bs[akq + 1][arow] = wv.y;
            Bs[akq + 2][arow] = wv.z; Bs[akq + 3][arow] = wv.w;
            __syncthreads();
#pragma unroll
            for (int kk = 0; kk < 16; kk++) {
                float4 av = *(const float4*)&As[kk][ty * 4];
                float4 bv = *(const float4*)&Bs[kk][tx * 4];
                float a[4] = {av.x, av.y, av.z, av.w};
                float bb[4] = {bv.x, bv.y, bv.z, bv.w};
#pragma unroll
                for (int i = 0; i < 4; i++)
#pragma unroll
                    for (int j = 0; j < 4; j++) acc[i][j] += a[i] * bb[j];
            }
            __syncthreads();
        }
    }
#pragma unroll
    for (int j = 0; j < 4; j++) {
        int c = c0 + tx * 4 + j;
        float bvv = bias[c];
#pragma unroll
        for (int i = 0; i < 4; i++) {
            int t = t0 + ty * 4 + i;
            float v = acc[i][j] + bvv;
            Y[((long)b * C1_ + c) * T_ + t] = v > 0.f ? v : 0.f;
        }
    }
}

// ---------- conv2: [B,C1,T] -> [B,2,T] ----------
__global__ void conv2_kernel(const float* __restrict__ A1, const float* __restrict__ W2,
                             const float* __restrict__ b2, float* __restrict__ A2)
{
    int b = blockIdx.y;
    int t = blockIdx.x * blockDim.x + threadIdx.x;
    float acc0 = b2[0], acc1 = b2[1];
    const float* base = A1 + (long)b * C1_ * T_;
    for (int c = 0; c < C1_; c++) {
        const float* row = base + (long)c * T_;
        float xm = (t >= 1)      ? row[t - 1] : 0.f;
        float x0 = row[t];
        float xp = (t <= T_ - 2) ? row[t + 1] : 0.f;
        const float* w0 = W2 + c * 3;
        const float* w1 = W2 + (C1_ + c) * 3;
        acc0 += xm * w0[0] + x0 * w0[1] + xp * w0[2];
        acc1 += xm * w1[0] + x0 * w1[1] + xp * w1[2];
    }
    A2[((long)b * 2 + 0) * T_ + t] = acc0;
    A2[((long)b * 2 + 1) * T_ + t] = acc1;
}

static float* sym(const void* s)
{
    void* p = nullptr;
    cudaGetSymbolAddress(&p, (const void*)s);
    return (float*)p;
}

extern "C" void kernel_launch(void* const* d_in, const int* in_sizes, int n_in,
                              void* d_out, int out_size)
{
    const float* x     = (const float*)d_in[0];
    const float* w_in1 = (const float*)d_in[1];
    const float* b_in1 = (const float*)d_in[2];
    const float* w_in2 = (const float*)d_in[3];
    const float* b_in2 = (const float*)d_in[4];
    const float* w_q   = (const float*)d_in[5];
    const float* b_q   = (const float*)d_in[6];
    const float* w_k   = (const float*)d_in[7];
    const float* b_k   = (const float*)d_in[8];
    const float* w_v   = (const float*)d_in[9];
    const float* b_v   = (const float*)d_in[10];
    const float* w_p   = (const float*)d_in[11];
    const float* b_p   = (const float*)d_in[12];
    const float* ln_g  = (const float*)d_in[13];
    const float* ln_b  = (const float*)d_in[14];
    const float* w_ih  = (const float*)d_in[15];
    const float* w_hh  = (const float*)d_in[16];
    const float* b_ih  = (const float*)d_in[17];
    const float* b_hh  = (const float*)d_in[18];
    const float* w_c1  = (const float*)d_in[19];
    const float* b_c1  = (const float*)d_in[20];
    const float* w_c2  = (const float*)d_in[21];
    const float* b_c2  = (const float*)d_in[22];
    float* out = (float*)d_out;

    float* h1   = sym(g_h1);
    float* hh   = sym(g_hh);
    float* q    = sym(g_q);
    float* k    = sym(g_k);
    float* v    = sym(g_v);
    float* sc   = sym(g_sc);
    float* o    = sym(g_o);
    float* y    = sym(g_y);
    float* gx   = sym(g_gx);
    float* lstm = sym(g_lstm);
    float* hbuf = sym(g_hbuf);
    float* a1   = sym(g_a1);
    float* a2   = sym(g_a2);
    float* wc1t = sym(g_wc1t);

    dim3 blk(256);

    // in_pro: 1x1 -> leaky -> 1x1
    gemm_kernel<1,1,1><<<dim3(8,128,1), blk>>>(x, w_in1, b_in1, h1,
        BT_, E_, E_, E_, E_, E_, 1, 0,0,0,0,0,0);
    gemm_kernel<0,1,1><<<dim3(8,128,1), blk>>>(h1, w_in2, b_in2, hh,
        BT_, E_, E_, E_, E_, E_, 1, 0,0,0,0,0,0);

    // QKV
    gemm_kernel<0,1,1><<<dim3(16,128,1), blk>>>(hh, w_q, b_q, q,
        BT_, NH_*QD_, E_, E_, E_, NH_*QD_, 1, 0,0,0,0,0,0);
    gemm_kernel<0,1,1><<<dim3(16,128,1), blk>>>(hh, w_k, b_k, k,
        BT_, NH_*QD_, E_, E_, E_, NH_*QD_, 1, 0,0,0,0,0,0);
    gemm_kernel<0,1,1><<<dim3(32,128,1), blk>>>(hh, w_v, b_v, v,
        BT_, NH_*VD_, E_, E_, E_, NH_*VD_, 1, 0,0,0,0,0,0);

    // scores = q @ k^T per (b, head)
    gemm_kernel<0,1,0><<<dim3(16,16,B_*NH_), blk>>>(q, k, nullptr, sc,
        T_, T_, QD_, NH_*QD_, NH_*QD_, T_, NH_,
        (long)T_*NH_*QD_, (long)QD_, (long)T_*NH_*QD_, (long)QD_,
        (long)NH_*T_*T_, (long)T_*T_);

    softmax_kernel<<<B_*NH_*T_, 256>>>(sc);

    // o = attn @ v per (b, head)
    gemm_kernel<0,0,0><<<dim3(8,16,B_*NH_), blk>>>(sc, v, nullptr, o,
        T_, VD_, T_, T_, NH_*VD_, NH_*VD_, NH_,
        (long)NH_*T_*T_, (long)T_*T_, (long)T_*NH_*VD_, (long)VD_,
        (long)T_*NH_*VD_, (long)VD_);

    // out projection + layernorm
    gemm_kernel<0,1,1><<<dim3(8,128,1), blk>>>(o, w_p, b_p, y,
        BT_, E_, NH_*VD_, NH_*VD_, NH_*VD_, E_, 1, 0,0,0,0,0,0);
    layernorm_kernel<<<BT_, 128>>>(y, ln_g, ln_b, y);

    // LSTM input GEMM: gx = y @ w_ih^T + b_ih
    gemm_kernel<0,1,1><<<dim3(64,128,1), blk>>>(y, w_ih, b_ih, gx,
        BT_, G4_, E_, E_, E_, G4_, 1, 0,0,0,0,0,0);

    reset_kernel<<<64, 256>>>();
    lstm_kernel<<<LSTM_NB, 256>>>(gx, w_hh, b_hh, hbuf, lstm);

    // conv pooling
    repack_wc1<<<(C1_*H_*3 + 255)/256, 256>>>(w_c1, wc1t);
    conv1_kernel<<<dim3(8,16,B_), blk>>>(lstm, wc1t, b_c1, a1);
    conv2_kernel<<<dim3(4,B_), 256>>>(a1, w_c2, b_c2, a2);
    softmax_kernel<<<B_*C2_, 256>>>(a2);

    // feat = a2 @ lstm_out : [2,1024]@[1024,1024] per batch -> out [8,2048]
    gemm_kernel<0,0,0><<<dim3(16,1,B_), blk>>>(a2, lstm, nullptr, out,
        C2_, H_, T_, T_, H_, H_, 1,
        (long)C2_*T_, 0, (long)T_*H_, 0, (long)C2_*H_, 0);
}

// round 5
// speedup vs baseline: 1.0672x; 1.0672x over previous
#include <cuda_runtime.h>

#define B_   8
#define T_   1024
#define E_   512
#define H_   1024
#define NH_  4
#define QD_  256
#define VD_  512
#define C1_  512
#define C2_  2
#define BT_  (B_ * T_)
#define G4_  (4 * H_)

__device__ float g_h1[(size_t)BT_ * E_];
__device__ float g_hh[(size_t)BT_ * E_];
__device__ float g_q [(size_t)BT_ * (NH_ * QD_)];
__device__ float g_k [(size_t)BT_ * (NH_ * QD_)];
__device__ float g_v [(size_t)BT_ * (NH_ * VD_)];
__device__ float g_sc[(size_t)B_ * NH_ * T_ * T_];
__device__ float g_o [(size_t)BT_ * (NH_ * VD_)];
__device__ float g_y [(size_t)BT_ * E_];
__device__ float g_gx[(size_t)BT_ * G4_];
__device__ float g_lstm[(size_t)BT_ * H_];
__device__ float g_hbuf[2 * B_ * H_];
__device__ float g_a1[(size_t)B_ * C1_ * T_];
__device__ float g_a2[(size_t)B_ * C2_ * T_];
__device__ float g_wc1t[(size_t)3 * C1_ * H_];
__device__ unsigned g_bar;
__device__ unsigned g_rel;

__device__ __forceinline__ float2 ffma2(float2 a, float2 b, float2 c)
{
    unsigned long long A = *reinterpret_cast<unsigned long long*>(&a);
    unsigned long long Bb = *reinterpret_cast<unsigned long long*>(&b);
    unsigned long long Cc = *reinterpret_cast<unsigned long long*>(&c);
    unsigned long long D;
    asm("fma.rn.f32x2 %0, %1, %2, %3;" : "=l"(D) : "l"(A), "l"(Bb), "l"(Cc));
    return *reinterpret_cast<float2*>(&D);
}

// ================= 128x128 tile SGEMM with packed f32x2 FMA =================
// C = act(A @ op(B) + bias). A:[M,K] row-major. TRANSB=1: B:[N,K]; 0: B:[K,N].
// Requires: M%128==0, N%128==0, K%16==0.
template<int ACT, int TRANSB, int HASBIAS>
__global__ __launch_bounds__(256)
void gemm128(const float* __restrict__ A, const float* __restrict__ Bm,
             const float* __restrict__ bias, float* __restrict__ C,
             int M, int N, int Kd, int lda, int ldb, int ldc,
             int bInner, long sAo, long sAi, long sBo, long sBi,
             long sCo, long sCi)
{
    int z  = blockIdx.z;
    int zo = z / bInner, zi = z % bInner;
    A  += zo * sAo + zi * sAi;
    Bm += zo * sBo + zi * sBi;
    C  += zo * sCo + zi * sCi;

    __shared__ float As[16][128];
    __shared__ float Bs[16][128];

    const int tid = threadIdx.x;
    const int tx = tid & 15, ty = tid >> 4;
    const int m0 = blockIdx.y * 128, n0 = blockIdx.x * 128;
    const int lm = tid >> 1;            // 0..127
    const int lk = (tid & 1) * 8;       // 0 / 8

    float2 acc[4][8];
#pragma unroll
    for (int p = 0; p < 4; p++)
#pragma unroll
        for (int j = 0; j < 8; j++) acc[p][j] = make_float2(0.f, 0.f);

    for (int k0 = 0; k0 < Kd; k0 += 16) {
        {   // A tile -> As[k][m]
            const float* ap = &A[(long)(m0 + lm) * lda + k0 + lk];
            float4 a0 = *(const float4*)ap;
            float4 a1 = *(const float4*)(ap + 4);
            As[lk + 0][lm] = a0.x; As[lk + 1][lm] = a0.y;
            As[lk + 2][lm] = a0.z; As[lk + 3][lm] = a0.w;
            As[lk + 4][lm] = a1.x; As[lk + 5][lm] = a1.y;
            As[lk + 6][lm] = a1.z; As[lk + 7][lm] = a1.w;
        }
        if (TRANSB) {
            const float* bp = &Bm[(long)(n0 + lm) * ldb + k0 + lk];
            float4 b0 = *(const float4*)bp;
            float4 b1 = *(const float4*)(bp + 4);
            Bs[lk + 0][lm] = b0.x; Bs[lk + 1][lm] = b0.y;
            Bs[lk + 2][lm] = b0.z; Bs[lk + 3][lm] = b0.w;
            Bs[lk + 4][lm] = b1.x; Bs[lk + 5][lm] = b1.y;
            Bs[lk + 6][lm] = b1.z; Bs[lk + 7][lm] = b1.w;
        } else {
            int r = tid >> 4, c = (tid & 15) * 8;
            const float* bp = &Bm[(long)(k0 + r) * ldb + n0 + c];
            *(float4*)&Bs[r][c]     = *(const float4*)bp;
            *(float4*)&Bs[r][c + 4] = *(const float4*)(bp + 4);
        }
        __syncthreads();
#pragma unroll
        for (int kk = 0; kk < 16; kk++) {
            float4 av0 = *(const float4*)&As[kk][ty * 8];
            float4 av1 = *(const float4*)&As[kk][ty * 8 + 4];
            float2 a2[4] = { make_float2(av0.x, av0.y), make_float2(av0.z, av0.w),
                             make_float2(av1.x, av1.y), make_float2(av1.z, av1.w) };
            float4 bv0 = *(const float4*)&Bs[kk][tx * 8];
            float4 bv1 = *(const float4*)&Bs[kk][tx * 8 + 4];
            float bj[8] = { bv0.x, bv0.y, bv0.z, bv0.w, bv1.x, bv1.y, bv1.z, bv1.w };
#pragma unroll
            for (int j = 0; j < 8; j++) {
                float2 b2 = make_float2(bj[j], bj[j]);
#pragma unroll
                for (int p = 0; p < 4; p++) acc[p][j] = ffma2(a2[p], b2, acc[p][j]);
            }
        }
        __syncthreads();
    }

    const int n = n0 + tx * 8;
    float bb[8];
#pragma unroll
    for (int j = 0; j < 8; j++) bb[j] = HASBIAS ? bias[n + j] : 0.f;
#pragma unroll
    for (int p = 0; p < 4; p++) {
        int m = m0 + ty * 8 + 2 * p;
        float r0[8], r1[8];
#pragma unroll
        for (int j = 0; j < 8; j++) {
            float v0 = acc[p][j].x + bb[j];
            float v1 = acc[p][j].y + bb[j];
            if (ACT == 1) { v0 = v0 >= 0.f ? v0 : 0.25f * v0; v1 = v1 >= 0.f ? v1 : 0.25f * v1; }
            r0[j] = v0; r1[j] = v1;
        }
        *(float4*)&C[(long)m * ldc + n]           = make_float4(r0[0], r0[1], r0[2], r0[3]);
        *(float4*)&C[(long)m * ldc + n + 4]       = make_float4(r0[4], r0[5], r0[6], r0[7]);
        *(float4*)&C[(long)(m + 1) * ldc + n]     = make_float4(r1[0], r1[1], r1[2], r1[3]);
        *(float4*)&C[(long)(m + 1) * ldc + n + 4] = make_float4(r1[4], r1[5], r1[6], r1[7]);
    }
}

// ---------- old 64x64 SGEMM kept only for the tiny final pooling GEMM ----------
template<int ACT, int TRANSB, int HASBIAS>
__global__ __launch_bounds__(256)
void gemm_kernel(const float* __restrict__ A, const float* __restrict__ Bm,
                 const float* __restrict__ bias, float* __restrict__ C,
                 int M, int N, int Kd, int lda, int ldb, int ldc,
                 int bInner, long sAo, long sAi, long sBo, long sBi,
                 long sCo, long sCi)
{
    int z  = blockIdx.z;
    int zo = z / bInner, zi = z % bInner;
    A  += zo * sAo + zi * sAi;
    Bm += zo * sBo + zi * sBi;
    C  += zo * sCo + zi * sCi;

    __shared__ float As[16][64];
    __shared__ float Bs[16][64];

    int tid = threadIdx.x;
    int tx = tid & 15, ty = tid >> 4;
    int m0 = blockIdx.y * 64, n0 = blockIdx.x * 64;
    int arow = tid >> 2, akq = (tid & 3) * 4;

    float acc[4][4];
#pragma unroll
    for (int i = 0; i < 4; i++)
#pragma unroll
        for (int j = 0; j < 4; j++) acc[i][j] = 0.f;

    for (int k0 = 0; k0 < Kd; k0 += 16) {
        {
            int m = m0 + arow;
            float4 v = make_float4(0.f, 0.f, 0.f, 0.f);
            if (m < M) v = *(const float4*)&A[(long)m * lda + k0 + akq];
            As[akq + 0][arow] = v.x; As[akq + 1][arow] = v.y;
            As[akq + 2][arow] = v.z; As[akq + 3][arow] = v.w;
        }
        if (TRANSB) {
            int nn = n0 + arow;
            float4 v = make_float4(0.f, 0.f, 0.f, 0.f);
            if (nn < N) v = *(const float4*)&Bm[(long)nn * ldb + k0 + akq];
            Bs[akq + 0][arow] = v.x; Bs[akq + 1][arow] = v.y;
            Bs[akq + 2][arow] = v.z; Bs[akq + 3][arow] = v.w;
        } else {
#pragma unroll
            for (int p = 0; p < 4; p++) {
                int kk = (tid >> 6) + p * 4;
                int nn = n0 + (tid & 63);
                float v = 0.f;
                if (nn < N) v = Bm[(long)(k0 + kk) * ldb + nn];
                Bs[kk][tid & 63] = v;
            }
        }
        __syncthreads();
#pragma unroll
        for (int kk = 0; kk < 16; kk++) {
            float4 av = *(const float4*)&As[kk][ty * 4];
            float4 bv = *(const float4*)&Bs[kk][tx * 4];
            float a[4] = {av.x, av.y, av.z, av.w};
            float b[4] = {bv.x, bv.y, bv.z, bv.w};
#pragma unroll
            for (int i = 0; i < 4; i++)
#pragma unroll
                for (int j = 0; j < 4; j++) acc[i][j] += a[i] * b[j];
        }
        __syncthreads();
    }
#pragma unroll
    for (int i = 0; i < 4; i++) {
        int m = m0 + ty * 4 + i;
        if (m >= M) continue;
#pragma unroll
        for (int j = 0; j < 4; j++) {
            int nn = n0 + tx * 4 + j;
            if (nn >= N) continue;
            float v = acc[i][j];
            if (HASBIAS) v += bias[nn];
            if (ACT == 1) v = v >= 0.f ? v : 0.25f * v;
            C[(long)m * ldc + nn] = v;
        }
    }
}

// ---------- softmax over rows of 1024 (in place), 256 threads ----------
__global__ void softmax_kernel(float* __restrict__ data)
{
    long row = blockIdx.x;
    float4* p = (float4*)(data + row * 1024);
    float4 v = p[threadIdx.x];
    int lane = threadIdx.x & 31, w = threadIdx.x >> 5;
    __shared__ float sm[8], ss[8];

    float m = fmaxf(fmaxf(v.x, v.y), fmaxf(v.z, v.w));
#pragma unroll
    for (int o = 16; o; o >>= 1) m = fmaxf(m, __shfl_xor_sync(0xffffffffu, m, o));
    if (lane == 0) sm[w] = m;
    __syncthreads();
    float bm = sm[0];
#pragma unroll
    for (int i = 1; i < 8; i++) bm = fmaxf(bm, sm[i]);

    v.x = __expf(v.x - bm); v.y = __expf(v.y - bm);
    v.z = __expf(v.z - bm); v.w = __expf(v.w - bm);
    float s = v.x + v.y + v.z + v.w;
#pragma unroll
    for (int o = 16; o; o >>= 1) s += __shfl_xor_sync(0xffffffffu, s, o);
    if (lane == 0) ss[w] = s;
    __syncthreads();
    float bs = ss[0] + ss[1] + ss[2] + ss[3] + ss[4] + ss[5] + ss[6] + ss[7];
    float inv = 1.f / bs;
    v.x *= inv; v.y *= inv; v.z *= inv; v.w *= inv;
    p[threadIdx.x] = v;
}

// ---------- LayerNorm over E=512, 128 threads ----------
__global__ void layernorm_kernel(const float* __restrict__ x, const float* __restrict__ g,
                                 const float* __restrict__ bta, float* __restrict__ y)
{
    long row = blockIdx.x;
    const float4* xr = (const float4*)(x + row * 512);
    float4 v = xr[threadIdx.x];
    int lane = threadIdx.x & 31, w = threadIdx.x >> 5;
    float s1 = v.x + v.y + v.z + v.w;
    float s2 = v.x * v.x + v.y * v.y + v.z * v.z + v.w * v.w;
#pragma unroll
    for (int o = 16; o; o >>= 1) {
        s1 += __shfl_xor_sync(0xffffffffu, s1, o);
        s2 += __shfl_xor_sync(0xffffffffu, s2, o);
    }
    __shared__ float a1s[4], a2s[4];
    if (lane == 0) { a1s[w] = s1; a2s[w] = s2; }
    __syncthreads();
    s1 = a1s[0] + a1s[1] + a1s[2] + a1s[3];
    s2 = a2s[0] + a2s[1] + a2s[2] + a2s[3];
    float mean = s1 * (1.f / 512.f);
    float var  = s2 * (1.f / 512.f) - mean * mean;
    float inv  = rsqrtf(var + 1e-5f);
    float4 gv = ((const float4*)g)[threadIdx.x];
    float4 bv = ((const float4*)bta)[threadIdx.x];
    float4 o4;
    o4.x = (v.x - mean) * inv * gv.x + bv.x;
    o4.y = (v.y - mean) * inv * gv.y + bv.y;
    o4.z = (v.z - mean) * inv * gv.z + bv.z;
    o4.w = (v.w - mean) * inv * gv.w + bv.w;
    ((float4*)(y + row * 512))[threadIdx.x] = o4;
}

__global__ void reset_kernel()
{
    int i = blockIdx.x * blockDim.x + threadIdx.x;
    if (i < 2 * B_ * H_) g_hbuf[i] = 0.f;
    if (i == 0) { g_bar = 0u; g_rel = 0u; }
}

__device__ __forceinline__ float fsigmoid(float x) { return 1.f / (1.f + __expf(-x)); }
__device__ __forceinline__ float ftanh(float x)
{
    float e = __expf(2.f * x);
    return 1.f - 2.f / (e + 1.f);
}

#define LSTM_NB 128
__global__ __launch_bounds__(256, 1)
void lstm_kernel(const float* __restrict__ gx, const float* __restrict__ Whh,
                 const float* __restrict__ bhh, float* __restrict__ hbuf,
                 float* __restrict__ lstm_out)
{
    const int tid  = threadIdx.x;
    const int lane = tid & 31;
    const int w    = tid >> 5;
    const int bi   = blockIdx.x;

    __shared__ float sh[8][1024];
    __shared__ float sg[32][8];
    __shared__ float scs[8][8];

    float2 wreg[4][16];
#pragma unroll
    for (int r = 0; r < 4; r++) {
        int lr = w * 4 + r;
        int j  = (lr >> 3) * H_ + bi * 8 + (lr & 7);
        const float2* wrow = (const float2*)(Whh + (long)j * H_);
#pragma unroll
        for (int kk = 0; kk < 16; kk++) wreg[r][kk] = wrow[kk * 32 + lane];
    }
    if (tid < 64) scs[tid >> 3][tid & 7] = 0.f;

    unsigned target = 0;
    for (int t = 0; t < T_; t++) {
        const float4* hr = (const float4*)(hbuf + (t & 1) * (B_ * H_));
        float*        hw =                 hbuf + ((t + 1) & 1) * (B_ * H_);
#pragma unroll
        for (int p = 0; p < 8; p++)
            ((float4*)&sh[0][0])[tid + p * 256] = hr[tid + p * 256];
        __syncthreads();

#pragma unroll
        for (int bh = 0; bh < 2; bh++) {
            float2 acc[4][4];
#pragma unroll
            for (int r = 0; r < 4; r++)
#pragma unroll
                for (int b = 0; b < 4; b++) acc[r][b] = make_float2(0.f, 0.f);
#pragma unroll
            for (int kk = 0; kk < 16; kk++) {
                float2 h2[4];
#pragma unroll
                for (int b = 0; b < 4; b++)
                    h2[b] = *(const float2*)&sh[bh * 4 + b][kk * 64 + lane * 2];
#pragma unroll
                for (int r = 0; r < 4; r++) {
                    float2 wv = wreg[r][kk];
#pragma unroll
                    for (int b = 0; b < 4; b++) acc[r][b] = ffma2(wv, h2[b], acc[r][b]);
                }
            }
#pragma unroll
            for (int r = 0; r < 4; r++)
#pragma unroll
                for (int b = 0; b < 4; b++) {
                    float s = acc[r][b].x + acc[r][b].y;
#pragma unroll
                    for (int o = 16; o; o >>= 1) s += __shfl_xor_sync(0xffffffffu, s, o);
                    if (lane == r * 4 + b) sg[w * 4 + r][bh * 4 + b] = s;
                }
        }
        __syncthreads();

        if (tid < 64) {
            int ul = tid >> 3, b = tid & 7;
            int u  = bi * 8 + ul;
            long grow = ((long)b * T_ + t) * G4_;
            float gi = sg[0 * 8 + ul][b] + gx[grow + 0 * H_ + u] + bhh[0 * H_ + u];
            float gf = sg[1 * 8 + ul][b] + gx[grow + 1 * H_ + u] + bhh[1 * H_ + u];
            float gg = sg[2 * 8 + ul][b] + gx[grow + 2 * H_ + u] + bhh[2 * H_ + u];
            float go = sg[3 * 8 + ul][b] + gx[grow + 3 * H_ + u] + bhh[3 * H_ + u];
            float c  = fsigmoid(gf) * scs[ul][b] + fsigmoid(gi) * ftanh(gg);
            float hn = fsigmoid(go) * ftanh(c);
            scs[ul][b] = c;
            hw[b * H_ + u] = hn;
            lstm_out[((long)b * T_ + t) * H_ + u] = hn;
            __threadfence();
        }
        __syncthreads();

        target += LSTM_NB;
        if (tid == 0) {
            unsigned arr = atomicAdd(&g_bar, 1u) + 1u;
            if (arr == target) {
                atomicExch(&g_rel, target);
            } else {
                unsigned r;
                do {
                    asm volatile("ld.global.acquire.gpu.u32 %0, [%1];"
                                 : "=r"(r) : "l"(&g_rel));
                } while (r < target);
            }
            __threadfence();
        }
        __syncthreads();
    }
}

// ---------- conv weight repack: w[c][h][dk] -> wt[dk][c][h] ----------
__global__ void repack_wc1(const float* __restrict__ w, float* __restrict__ wt)
{
    int idx = blockIdx.x * blockDim.x + threadIdx.x;
    if (idx < C1_ * H_ * 3) {
        int dk = idx % 3;
        int h  = (idx / 3) % H_;
        int c  = idx / (3 * H_);
        wt[(long)dk * C1_ * H_ + (long)c * H_ + h] = w[idx];
    }
}

// ---------- conv1 via 128x128 f32x2 tiles: relu(conv(lstm_out)) -> [B,C1,T] ----------
__global__ __launch_bounds__(256)
void conv1_kernel(const float* __restrict__ X, const float* __restrict__ Wt,
                  const float* __restrict__ bias, float* __restrict__ Y)
{
    const int b  = blockIdx.z;
    const int t0 = blockIdx.y * 128, c0 = blockIdx.x * 128;
    __shared__ float As[16][128];
    __shared__ float Bs[16][128];
    const int tid = threadIdx.x;
    const int tx = tid & 15, ty = tid >> 4;
    const int lm = tid >> 1;
    const int lk = (tid & 1) * 8;

    float2 acc[4][8];
#pragma unroll
    for (int p = 0; p < 4; p++)
#pragma unroll
        for (int j = 0; j < 8; j++) acc[p][j] = make_float2(0.f, 0.f);

    for (int dk = 0; dk < 3; dk++) {
        const float* Wd = Wt + (long)dk * C1_ * H_;
        for (int k0 = 0; k0 < H_; k0 += 16) {
            {
                int t = t0 + lm + dk - 1;
                float4 a0 = make_float4(0.f, 0.f, 0.f, 0.f), a1 = a0;
                if (t >= 0 && t < T_) {
                    const float* ap = &X[((long)b * T_ + t) * H_ + k0 + lk];
                    a0 = *(const float4*)ap;
                    a1 = *(const float4*)(ap + 4);
                }
                As[lk + 0][lm] = a0.x; As[lk + 1][lm] = a0.y;
                As[lk + 2][lm] = a0.z; As[lk + 3][lm] = a0.w;
                As[lk + 4][lm] = a1.x; As[lk + 5][lm] = a1.y;
                As[lk + 6][lm] = a1.z; As[lk + 7][lm] = a1.w;
            }
            {
                const float* bp = &Wd[(long)(c0 + lm) * H_ + k0 + lk];
                float4 b0 = *(const float4*)bp;
                float4 b1 = *(const float4*)(bp + 4);
                Bs[lk + 0][lm] = b0.x; Bs[lk + 1][lm] = b0.y;
                Bs[lk + 2][lm] = b0.z; Bs[lk + 3][lm] = b0.w;
                Bs[lk + 4][lm] = b1.x; Bs[lk + 5][lm] = b1.y;
                Bs[lk + 6][lm] = b1.z; Bs[lk + 7][lm] = b1.w;
            }
            __syncthreads();
#pragma unroll
            for (int kk = 0; kk < 16; kk++) {
                float4 av0 = *(const float4*)&As[kk][ty * 8];
                float4 av1 = *(const float4*)&As[kk][ty * 8 + 4];
                float2 a2[4] = { make_float2(av0.x, av0.y), make_float2(av0.z, av0.w),
                                 make_float2(av1.x, av1.y), make_float2(av1.z, av1.w) };
                float4 bv0 = *(const float4*)&Bs[kk][tx * 8];
                float4 bv1 = *(const float4*)&Bs[kk][tx * 8 + 4];
                float bj[8] = { bv0.x, bv0.y, bv0.z, bv0.w, bv1.x, bv1.y, bv1.z, bv1.w };
#pragma unroll
                for (int j = 0; j < 8; j++) {
                    float2 b2 = make_float2(bj[j], bj[j]);
#pragma unroll
                    for (int p = 0; p < 4; p++) acc[p][j] = ffma2(a2[p], b2, acc[p][j]);
                }
            }
            __syncthreads();
        }
    }
    // Y[b][c][t] = relu(acc + bias[c]); acc rows are t, cols are c -> scalar stores
#pragma unroll
    for (int j = 0; j < 8; j++) {
        int c = c0 + tx * 8 + j;
        float bvv = bias[c];
        float* yrow = &Y[((long)b * C1_ + c) * T_];
#pragma unroll
        for (int p = 0; p < 4; p++) {
            int t = t0 + ty * 8 + 2 * p;
            float v0 = acc[p][j].x + bvv;
            float v1 = acc[p][j].y + bvv;
            yrow[t]     = v0 > 0.f ? v0 : 0.f;
            yrow[t + 1] = v1 > 0.f ? v1 : 0.f;
        }
    }
}

// ---------- conv2: [B,C1,T] -> [B,2,T] ----------
__global__ void conv2_kernel(const float* __restrict__ A1, const float* __restrict__ W2,
                             const float* __restrict__ b2, float* __restrict__ A2)
{
    int b = blockIdx.y;
    int t = blockIdx.x * blockDim.x + threadIdx.x;
    float acc0 = b2[0], acc1 = b2[1];
    const float* base = A1 + (long)b * C1_ * T_;
    for (int c = 0; c < C1_; c++) {
        const float* row = base + (long)c * T_;
        float xm = (t >= 1)      ? row[t - 1] : 0.f;
        float x0 = row[t];
        float xp = (t <= T_ - 2) ? row[t + 1] : 0.f;
        const float* w0 = W2 + c * 3;
        const float* w1 = W2 + (C1_ + c) * 3;
        acc0 += xm * w0[0] + x0 * w0[1] + xp * w0[2];
        acc1 += xm * w1[0] + x0 * w1[1] + xp * w1[2];
    }
    A2[((long)b * 2 + 0) * T_ + t] = acc0;
    A2[((long)b * 2 + 1) * T_ + t] = acc1;
}

static float* sym(const void* s)
{
    void* p = nullptr;
    cudaGetSymbolAddress(&p, (const void*)s);
    return (float*)p;
}

extern "C" void kernel_launch(void* const* d_in, const int* in_sizes, int n_in,
                              void* d_out, int out_size)
{
    const float* x     = (const float*)d_in[0];
    const float* w_in1 = (const float*)d_in[1];
    const float* b_in1 = (const float*)d_in[2];
    const float* w_in2 = (const float*)d_in[3];
    const float* b_in2 = (const float*)d_in[4];
    const float* w_q   = (const float*)d_in[5];
    const float* b_q   = (const float*)d_in[6];
    const float* w_k   = (const float*)d_in[7];
    const float* b_k   = (const float*)d_in[8];
    const float* w_v   = (const float*)d_in[9];
    const float* b_v   = (const float*)d_in[10];
    const float* w_p   = (const float*)d_in[11];
    const float* b_p   = (const float*)d_in[12];
    const float* ln_g  = (const float*)d_in[13];
    const float* ln_b  = (const float*)d_in[14];
    const float* w_ih  = (const float*)d_in[15];
    const float* w_hh  = (const float*)d_in[16];
    const float* b_ih  = (const float*)d_in[17];
    const float* b_hh  = (const float*)d_in[18];
    const float* w_c1  = (const float*)d_in[19];
    const float* b_c1  = (const float*)d_in[20];
    const float* w_c2  = (const float*)d_in[21];
    const float* b_c2  = (const float*)d_in[22];
    float* out = (float*)d_out;

    float* h1   = sym(g_h1);
    float* hh   = sym(g_hh);
    float* q    = sym(g_q);
    float* k    = sym(g_k);
    float* v    = sym(g_v);
    float* sc   = sym(g_sc);
    float* o    = sym(g_o);
    float* y    = sym(g_y);
    float* gx   = sym(g_gx);
    float* lstm = sym(g_lstm);
    float* hbuf = sym(g_hbuf);
    float* a1   = sym(g_a1);
    float* a2   = sym(g_a2);
    float* wc1t = sym(g_wc1t);

    dim3 blk(256);

    // in_pro: 1x1 -> leaky -> 1x1
    gemm128<1,1,1><<<dim3(4,64,1), blk>>>(x, w_in1, b_in1, h1,
        BT_, E_, E_, E_, E_, E_, 1, 0,0,0,0,0,0);
    gemm128<0,1,1><<<dim3(4,64,1), blk>>>(h1, w_in2, b_in2, hh,
        BT_, E_, E_, E_, E_, E_, 1, 0,0,0,0,0,0);

    // QKV
    gemm128<0,1,1><<<dim3(8,64,1), blk>>>(hh, w_q, b_q, q,
        BT_, NH_*QD_, E_, E_, E_, NH_*QD_, 1, 0,0,0,0,0,0);
    gemm128<0,1,1><<<dim3(8,64,1), blk>>>(hh, w_k, b_k, k,
        BT_, NH_*QD_, E_, E_, E_, NH_*QD_, 1, 0,0,0,0,0,0);
    gemm128<0,1,1><<<dim3(16,64,1), blk>>>(hh, w_v, b_v, v,
        BT_, NH_*VD_, E_, E_, E_, NH_*VD_, 1, 0,0,0,0,0,0);

    // scores = q @ k^T per (b, head)
    gemm128<0,1,0><<<dim3(8,8,B_*NH_), blk>>>(q, k, nullptr, sc,
        T_, T_, QD_, NH_*QD_, NH_*QD_, T_, NH_,
        (long)T_*NH_*QD_, (long)QD_, (long)T_*NH_*QD_, (long)QD_,
        (long)NH_*T_*T_, (long)T_*T_);

    softmax_kernel<<<B_*NH_*T_, 256>>>(sc);

    // o = attn @ v per (b, head)
    gemm128<0,0,0><<<dim3(4,8,B_*NH_), blk>>>(sc, v, nullptr, o,
        T_, VD_, T_, T_, NH_*VD_, NH_*VD_, NH_,
        (long)NH_*T_*T_, (long)T_*T_, (long)T_*NH_*VD_, (long)VD_,
        (long)T_*NH_*VD_, (long)VD_);

    // out projection + layernorm
    gemm128<0,1,1><<<dim3(4,64,1), blk>>>(o, w_p, b_p, y,
        BT_, E_, NH_*VD_, NH_*VD_, NH_*VD_, E_, 1, 0,0,0,0,0,0);
    layernorm_kernel<<<BT_, 128>>>(y, ln_g, ln_b, y);

    // LSTM input GEMM: gx = y @ w_ih^T + b_ih
    gemm128<0,1,1><<<dim3(32,64,1), blk>>>(y, w_ih, b_ih, gx,
        BT_, G4_, E_, E_, E_, G4_, 1, 0,0,0,0,0,0);

    reset_kernel<<<64, 256>>>();
    lstm_kernel<<<LSTM_NB, 256>>>(gx, w_hh, b_hh, hbuf, lstm);

    // conv pooling
    repack_wc1<<<(C1_*H_*3 + 255)/256, 256>>>(w_c1, wc1t);
    conv1_kernel<<<dim3(4,8,B_), blk>>>(lstm, wc1t, b_c1, a1);
    conv2_kernel<<<dim3(4,B_), 256>>>(a1, w_c2, b_c2, a2);
    softmax_kernel<<<B_*C2_, 256>>>(a2);

    // feat = a2 @ lstm_out : [2,1024]@[1024,1024] per batch -> out [8,2048]
    gemm_kernel<0,0,0><<<dim3(16,1,B_), blk>>>(a2, lstm, nullptr, out,
        C2_, H_, T_, T_, H_, H_, 1,
        (long)C2_*T_, 0, (long)T_*H_, 0, (long)C2_*H_, 0);
}

// round 7
// speedup vs baseline: 1.1422x; 1.0703x over previous
#include <cuda_runtime.h>

#define B_   8
#define T_   1024
#define E_   512
#define H_   1024
#define NH_  4
#define QD_  256
#define VD_  512
#define C1_  512
#define C2_  2
#define BT_  (B_ * T_)
#define G4_  (4 * H_)

__device__ float g_h1[(size_t)BT_ * E_];
__device__ float g_hh[(size_t)BT_ * E_];
__device__ float g_q [(size_t)BT_ * (NH_ * QD_)];
__device__ float g_k [(size_t)BT_ * (NH_ * QD_)];
__device__ float g_v [(size_t)BT_ * (NH_ * VD_)];
__device__ float g_sc[(size_t)B_ * NH_ * T_ * T_];
__device__ float g_o [(size_t)BT_ * (NH_ * VD_)];
__device__ float g_y [(size_t)BT_ * E_];
__device__ float g_gx[(size_t)BT_ * G4_];
__device__ float g_lstm[(size_t)BT_ * H_];
__device__ float g_hbuf[2 * B_ * H_];
__device__ float g_a1[(size_t)B_ * C1_ * T_];
__device__ float g_a2[(size_t)B_ * C2_ * T_];
__device__ float g_wc1t[(size_t)3 * C1_ * H_];
__device__ unsigned g_bar;

__device__ __forceinline__ float2 ffma2(float2 a, float2 b, float2 c)
{
    unsigned long long A = *reinterpret_cast<unsigned long long*>(&a);
    unsigned long long Bb = *reinterpret_cast<unsigned long long*>(&b);
    unsigned long long Cc = *reinterpret_cast<unsigned long long*>(&c);
    unsigned long long D;
    asm("fma.rn.f32x2 %0, %1, %2, %3;" : "=l"(D) : "l"(A), "l"(Bb), "l"(Cc));
    return *reinterpret_cast<float2*>(&D);
}

// ========== 128x128 SGEMM, f32x2 FMA, double-buffered smem ==========
// C = act(A @ op(B) + bias). A:[M,K] row-major. TRANSB=1: B:[N,K]; 0: B:[K,N].
// Requires: M%128==0, N%128==0, K%16==0.
template<int ACT, int TRANSB, int HASBIAS>
__global__ __launch_bounds__(256)
void gemm128(const float* __restrict__ A, const float* __restrict__ Bm,
             const float* __restrict__ bias, float* __restrict__ C,
             int M, int N, int Kd, int lda, int ldb, int ldc,
             int bInner, long sAo, long sAi, long sBo, long sBi,
             long sCo, long sCi)
{
    int z  = blockIdx.z;
    int zo = z / bInner, zi = z % bInner;
    A  += zo * sAo + zi * sAi;
    Bm += zo * sBo + zi * sBi;
    C  += zo * sCo + zi * sCi;

    __shared__ float As[2][16][128];
    __shared__ float Bs[2][16][128];

    const int tid = threadIdx.x;
    const int tx = tid & 15, ty = tid >> 4;
    const int m0 = blockIdx.y * 128, n0 = blockIdx.x * 128;
    const int lm = tid >> 1;           // 0..127
    const int lk = (tid & 1) * 8;      // 0 / 8
    const int br = tid >> 4;           // TRANSB=0: k-row 0..15
    const int bc = (tid & 15) * 8;     // TRANSB=0: n-col

    float2 acc[4][8];
#pragma unroll
    for (int p = 0; p < 4; p++)
#pragma unroll
        for (int j = 0; j < 8; j++) acc[p][j] = make_float2(0.f, 0.f);

    float ap[8], bp[8];
    // ---- load tile 0 into regs ----
    {
        const float* p = &A[(long)(m0 + lm) * lda + lk];
        float4 v0 = *(const float4*)p, v1 = *(const float4*)(p + 4);
        ap[0]=v0.x; ap[1]=v0.y; ap[2]=v0.z; ap[3]=v0.w;
        ap[4]=v1.x; ap[5]=v1.y; ap[6]=v1.z; ap[7]=v1.w;
    }
    if (TRANSB) {
        const float* p = &Bm[(long)(n0 + lm) * ldb + lk];
        float4 v0 = *(const float4*)p, v1 = *(const float4*)(p + 4);
        bp[0]=v0.x; bp[1]=v0.y; bp[2]=v0.z; bp[3]=v0.w;
        bp[4]=v1.x; bp[5]=v1.y; bp[6]=v1.z; bp[7]=v1.w;
    } else {
        const float* p = &Bm[(long)br * ldb + n0 + bc];
        float4 v0 = *(const float4*)p, v1 = *(const float4*)(p + 4);
        bp[0]=v0.x; bp[1]=v0.y; bp[2]=v0.z; bp[3]=v0.w;
        bp[4]=v1.x; bp[5]=v1.y; bp[6]=v1.z; bp[7]=v1.w;
    }
    // ---- store tile 0 to buffer 0 ----
#pragma unroll
    for (int i = 0; i < 8; i++) As[0][lk + i][lm] = ap[i];
    if (TRANSB) {
#pragma unroll
        for (int i = 0; i < 8; i++) Bs[0][lk + i][lm] = bp[i];
    } else {
        *(float4*)&Bs[0][br][bc]     = make_float4(bp[0], bp[1], bp[2], bp[3]);
        *(float4*)&Bs[0][br][bc + 4] = make_float4(bp[4], bp[5], bp[6], bp[7]);
    }
    __syncthreads();

    const int nst = Kd >> 4;
    for (int s = 0; s < nst; s++) {
        const int cur = s & 1, nxt = cur ^ 1;
        if (s + 1 < nst) {
            int k0 = (s + 1) << 4;
            {
                const float* p = &A[(long)(m0 + lm) * lda + k0 + lk];
                float4 v0 = *(const float4*)p, v1 = *(const float4*)(p + 4);
                ap[0]=v0.x; ap[1]=v0.y; ap[2]=v0.z; ap[3]=v0.w;
                ap[4]=v1.x; ap[5]=v1.y; ap[6]=v1.z; ap[7]=v1.w;
            }
            if (TRANSB) {
                const float* p = &Bm[(long)(n0 + lm) * ldb + k0 + lk];
                float4 v0 = *(const float4*)p, v1 = *(const float4*)(p + 4);
                bp[0]=v0.x; bp[1]=v0.y; bp[2]=v0.z; bp[3]=v0.w;
                bp[4]=v1.x; bp[5]=v1.y; bp[6]=v1.z; bp[7]=v1.w;
            } else {
                const float* p = &Bm[(long)(k0 + br) * ldb + n0 + bc];
                float4 v0 = *(const float4*)p, v1 = *(const float4*)(p + 4);
                bp[0]=v0.x; bp[1]=v0.y; bp[2]=v0.z; bp[3]=v0.w;
                bp[4]=v1.x; bp[5]=v1.y; bp[6]=v1.z; bp[7]=v1.w;
            }
        }
#pragma unroll
        for (int kk = 0; kk < 16; kk++) {
            float4 av0 = *(const float4*)&As[cur][kk][ty * 8];
            float4 av1 = *(const float4*)&As[cur][kk][ty * 8 + 4];
            float2 a2[4] = { make_float2(av0.x, av0.y), make_float2(av0.z, av0.w),
                             make_float2(av1.x, av1.y), make_float2(av1.z, av1.w) };
            float4 bv0 = *(const float4*)&Bs[cur][kk][tx * 8];
            float4 bv1 = *(const float4*)&Bs[cur][kk][tx * 8 + 4];
            float bj[8] = { bv0.x, bv0.y, bv0.z, bv0.w, bv1.x, bv1.y, bv1.z, bv1.w };
#pragma unroll
            for (int j = 0; j < 8; j++) {
                float2 b2 = make_float2(bj[j], bj[j]);
#pragma unroll
                for (int p = 0; p < 4; p++) acc[p][j] = ffma2(a2[p], b2, acc[p][j]);
            }
        }
        if (s + 1 < nst) {
#pragma unroll
            for (int i = 0; i < 8; i++) As[nxt][lk + i][lm] = ap[i];
            if (TRANSB) {
#pragma unroll
                for (int i = 0; i < 8; i++) Bs[nxt][lk + i][lm] = bp[i];
            } else {
                *(float4*)&Bs[nxt][br][bc]     = make_float4(bp[0], bp[1], bp[2], bp[3]);
                *(float4*)&Bs[nxt][br][bc + 4] = make_float4(bp[4], bp[5], bp[6], bp[7]);
            }
            __syncthreads();
        }
    }

    const int n = n0 + tx * 8;
    float bb[8];
#pragma unroll
    for (int j = 0; j < 8; j++) bb[j] = HASBIAS ? bias[n + j] : 0.f;
#pragma unroll
    for (int p = 0; p < 4; p++) {
        int m = m0 + ty * 8 + 2 * p;
        float r0[8], r1[8];
#pragma unroll
        for (int j = 0; j < 8; j++) {
            float v0 = acc[p][j].x + bb[j];
            float v1 = acc[p][j].y + bb[j];
            if (ACT == 1) { v0 = v0 >= 0.f ? v0 : 0.25f * v0; v1 = v1 >= 0.f ? v1 : 0.25f * v1; }
            r0[j] = v0; r1[j] = v1;
        }
        *(float4*)&C[(long)m * ldc + n]           = make_float4(r0[0], r0[1], r0[2], r0[3]);
        *(float4*)&C[(long)m * ldc + n + 4]       = make_float4(r0[4], r0[5], r0[6], r0[7]);
        *(float4*)&C[(long)(m + 1) * ldc + n]     = make_float4(r1[0], r1[1], r1[2], r1[3]);
        *(float4*)&C[(long)(m + 1) * ldc + n + 4] = make_float4(r1[4], r1[5], r1[6], r1[7]);
    }
}

// ---------- old 64x64 SGEMM kept only for the tiny final pooling GEMM ----------
template<int ACT, int TRANSB, int HASBIAS>
__global__ __launch_bounds__(256)
void gemm_kernel(const float* __restrict__ A, const float* __restrict__ Bm,
                 const float* __restrict__ bias, float* __restrict__ C,
                 int M, int N, int Kd, int lda, int ldb, int ldc,
                 int bInner, long sAo, long sAi, long sBo, long sBi,
                 long sCo, long sCi)
{
    int z  = blockIdx.z;
    int zo = z / bInner, zi = z % bInner;
    A  += zo * sAo + zi * sAi;
    Bm += zo * sBo + zi * sBi;
    C  += zo * sCo + zi * sCi;

    __shared__ float As[16][64];
    __shared__ float Bs[16][64];

    int tid = threadIdx.x;
    int tx = tid & 15, ty = tid >> 4;
    int m0 = blockIdx.y * 64, n0 = blockIdx.x * 64;
    int arow = tid >> 2, akq = (tid & 3) * 4;

    float acc[4][4];
#pragma unroll
    for (int i = 0; i < 4; i++)
#pragma unroll
        for (int j = 0; j < 4; j++) acc[i][j] = 0.f;

    for (int k0 = 0; k0 < Kd; k0 += 16) {
        {
            int m = m0 + arow;
            float4 v = make_float4(0.f, 0.f, 0.f, 0.f);
            if (m < M) v = *(const float4*)&A[(long)m * lda + k0 + akq];
            As[akq + 0][arow] = v.x; As[akq + 1][arow] = v.y;
            As[akq + 2][arow] = v.z; As[akq + 3][arow] = v.w;
        }
        if (TRANSB) {
            int nn = n0 + arow;
            float4 v = make_float4(0.f, 0.f, 0.f, 0.f);
            if (nn < N) v = *(const float4*)&Bm[(long)nn * ldb + k0 + akq];
            Bs[akq + 0][arow] = v.x; Bs[akq + 1][arow] = v.y;
            Bs[akq + 2][arow] = v.z; Bs[akq + 3][arow] = v.w;
        } else {
#pragma unroll
            for (int p = 0; p < 4; p++) {
                int kk = (tid >> 6) + p * 4;
                int nn = n0 + (tid & 63);
                float v = 0.f;
                if (nn < N) v = Bm[(long)(k0 + kk) * ldb + nn];
                Bs[kk][tid & 63] = v;
            }
        }
        __syncthreads();
#pragma unroll
        for (int kk = 0; kk < 16; kk++) {
            float4 av = *(const float4*)&As[kk][ty * 4];
            float4 bv = *(const float4*)&Bs[kk][tx * 4];
            float a[4] = {av.x, av.y, av.z, av.w};
            float b[4] = {bv.x, bv.y, bv.z, bv.w};
#pragma unroll
            for (int i = 0; i < 4; i++)
#pragma unroll
                for (int j = 0; j < 4; j++) acc[i][j] += a[i] * b[j];
        }
        __syncthreads();
    }
#pragma unroll
    for (int i = 0; i < 4; i++) {
        int m = m0 + ty * 4 + i;
        if (m >= M) continue;
#pragma unroll
        for (int j = 0; j < 4; j++) {
            int nn = n0 + tx * 4 + j;
            if (nn >= N) continue;
            float v = acc[i][j];
            if (HASBIAS) v += bias[nn];
            if (ACT == 1) v = v >= 0.f ? v : 0.25f * v;
            C[(long)m * ldc + nn] = v;
        }
    }
}

// ---------- softmax over rows of 1024 (in place), 256 threads ----------
__global__ void softmax_kernel(float* __restrict__ data)
{
    long row = blockIdx.x;
    float4* p = (float4*)(data + row * 1024);
    float4 v = p[threadIdx.x];
    int lane = threadIdx.x & 31, w = threadIdx.x >> 5;
    __shared__ float sm[8], ss[8];

    float m = fmaxf(fmaxf(v.x, v.y), fmaxf(v.z, v.w));
#pragma unroll
    for (int o = 16; o; o >>= 1) m = fmaxf(m, __shfl_xor_sync(0xffffffffu, m, o));
    if (lane == 0) sm[w] = m;
    __syncthreads();
    float bm = sm[0];
#pragma unroll
    for (int i = 1; i < 8; i++) bm = fmaxf(bm, sm[i]);

    v.x = __expf(v.x - bm); v.y = __expf(v.y - bm);
    v.z = __expf(v.z - bm); v.w = __expf(v.w - bm);
    float s = v.x + v.y + v.z + v.w;
#pragma unroll
    for (int o = 16; o; o >>= 1) s += __shfl_xor_sync(0xffffffffu, s, o);
    if (lane == 0) ss[w] = s;
    __syncthreads();
    float bs = ss[0] + ss[1] + ss[2] + ss[3] + ss[4] + ss[5] + ss[6] + ss[7];
    float inv = 1.f / bs;
    v.x *= inv; v.y *= inv; v.z *= inv; v.w *= inv;
    p[threadIdx.x] = v;
}

// ---------- LayerNorm over E=512, 128 threads ----------
__global__ void layernorm_kernel(const float* __restrict__ x, const float* __restrict__ g,
                                 const float* __restrict__ bta, float* __restrict__ y)
{
    long row = blockIdx.x;
    const float4* xr = (const float4*)(x + row * 512);
    float4 v = xr[threadIdx.x];
    int lane = threadIdx.x & 31, w = threadIdx.x >> 5;
    float s1 = v.x + v.y + v.z + v.w;
    float s2 = v.x * v.x + v.y * v.y + v.z * v.z + v.w * v.w;
#pragma unroll
    for (int o = 16; o; o >>= 1) {
        s1 += __shfl_xor_sync(0xffffffffu, s1, o);
        s2 += __shfl_xor_sync(0xffffffffu, s2, o);
    }
    __shared__ float a1s[4], a2s[4];
    if (lane == 0) { a1s[w] = s1; a2s[w] = s2; }
    __syncthreads();
    s1 = a1s[0] + a1s[1] + a1s[2] + a1s[3];
    s2 = a2s[0] + a2s[1] + a2s[2] + a2s[3];
    float mean = s1 * (1.f / 512.f);
    float var  = s2 * (1.f / 512.f) - mean * mean;
    float inv  = rsqrtf(var + 1e-5f);
    float4 gv = ((const float4*)g)[threadIdx.x];
    float4 bv = ((const float4*)bta)[threadIdx.x];
    float4 o4;
    o4.x = (v.x - mean) * inv * gv.x + bv.x;
    o4.y = (v.y - mean) * inv * gv.y + bv.y;
    o4.z = (v.z - mean) * inv * gv.z + bv.z;
    o4.w = (v.w - mean) * inv * gv.w + bv.w;
    ((float4*)(y + row * 512))[threadIdx.x] = o4;
}

__global__ void reset_kernel()
{
    int i = blockIdx.x * blockDim.x + threadIdx.x;
    if (i < 2 * B_ * H_) g_hbuf[i] = 0.f;
    if (i == 0) g_bar = 0u;
}

__device__ __forceinline__ float fsigmoid(float x) { return 1.f / (1.f + __expf(-x)); }
__device__ __forceinline__ float ftanh(float x)
{
    float e = __expf(2.f * x);
    return 1.f - 2.f / (e + 1.f);
}

#define LSTM_NB 128
__global__ __launch_bounds__(256, 1)
void lstm_kernel(const float* __restrict__ gx, const float* __restrict__ Whh,
                 const float* __restrict__ bhh, float* __restrict__ hbuf,
                 float* __restrict__ lstm_out)
{
    const int tid  = threadIdx.x;
    const int lane = tid & 31;
    const int w    = tid >> 5;
    const int bi   = blockIdx.x;

    __shared__ float sh[8][1024];
    __shared__ float sg[32][8];
    __shared__ float scs[8][8];

    float2 wreg[4][16];
#pragma unroll
    for (int r = 0; r < 4; r++) {
        int lr = w * 4 + r;
        int j  = (lr >> 3) * H_ + bi * 8 + (lr & 7);
        const float2* wrow = (const float2*)(Whh + (long)j * H_);
#pragma unroll
        for (int kk = 0; kk < 16; kk++) wreg[r][kk] = wrow[kk * 32 + lane];
    }

    // per-thread (tid<64) constants: unit index + recurrent biases
    int ul = tid >> 3, bb = tid & 7;
    int u  = bi * 8 + ul;
    float rb0 = 0.f, rb1 = 0.f, rb2 = 0.f, rb3 = 0.f;
    if (tid < 64) {
        rb0 = bhh[0 * H_ + u]; rb1 = bhh[1 * H_ + u];
        rb2 = bhh[2 * H_ + u]; rb3 = bhh[3 * H_ + u];
        scs[ul][bb] = 0.f;
    }

    unsigned target = 0;
    for (int t = 0; t < T_; t++) {
        // prefetch this step's gx early (independent of h)
        float px0, px1, px2, px3;
        if (tid < 64) {
            long grow = ((long)bb * T_ + t) * G4_;
            px0 = gx[grow + 0 * H_ + u];
            px1 = gx[grow + 1 * H_ + u];
            px2 = gx[grow + 2 * H_ + u];
            px3 = gx[grow + 3 * H_ + u];
        }

        const float4* hr = (const float4*)(hbuf + (t & 1) * (B_ * H_));
        float*        hw =                 hbuf + ((t + 1) & 1) * (B_ * H_);
#pragma unroll
        for (int p = 0; p < 8; p++)
            ((float4*)&sh[0][0])[tid + p * 256] = hr[tid + p * 256];
        __syncthreads();

#pragma unroll
        for (int bh = 0; bh < 2; bh++) {
            float2 acc[4][4];
#pragma unroll
            for (int r = 0; r < 4; r++)
#pragma unroll
                for (int b = 0; b < 4; b++) acc[r][b] = make_float2(0.f, 0.f);
#pragma unroll
            for (int kk = 0; kk < 16; kk++) {
                float2 h2[4];
#pragma unroll
                for (int b = 0; b < 4; b++)
                    h2[b] = *(const float2*)&sh[bh * 4 + b][kk * 64 + lane * 2];
#pragma unroll
                for (int r = 0; r < 4; r++) {
                    float2 wv = wreg[r][kk];
#pragma unroll
                    for (int b = 0; b < 4; b++) acc[r][b] = ffma2(wv, h2[b], acc[r][b]);
                }
            }
#pragma unroll
            for (int r = 0; r < 4; r++)
#pragma unroll
                for (int b = 0; b < 4; b++) {
                    float s = acc[r][b].x + acc[r][b].y;
#pragma unroll
                    for (int o = 16; o; o >>= 1) s += __shfl_xor_sync(0xffffffffu, s, o);
                    if (lane == r * 4 + b) sg[w * 4 + r][bh * 4 + b] = s;
                }
        }
        __syncthreads();

        if (tid < 64) {
            float gi = sg[0 * 8 + ul][bb] + px0 + rb0;
            float gf = sg[1 * 8 + ul][bb] + px1 + rb1;
            float gg = sg[2 * 8 + ul][bb] + px2 + rb2;
            float go = sg[3 * 8 + ul][bb] + px3 + rb3;
            float c  = fsigmoid(gf) * scs[ul][bb] + fsigmoid(gi) * ftanh(gg);
            float hn = fsigmoid(go) * ftanh(c);
            scs[ul][bb] = c;
            hw[bb * H_ + u] = hn;
            lstm_out[((long)bb * T_ + t) * H_ + u] = hn;
        }
        __syncthreads();

        target += LSTM_NB;
        if (tid == 0) {
            asm volatile("fence.acq_rel.gpu;" ::: "memory");
            atomicAdd(&g_bar, 1u);
            unsigned r;
            do {
                asm volatile("ld.global.acquire.gpu.u32 %0, [%1];"
                             : "=r"(r) : "l"(&g_bar));
            } while (r < target);
        }
        __syncthreads();
    }
}

// ---------- conv weight repack: w[c][h][dk] -> wt[dk][c][h] ----------
__global__ void repack_wc1(const float* __restrict__ w, float* __restrict__ wt)
{
    int idx = blockIdx.x * blockDim.x + threadIdx.x;
    if (idx < C1_ * H_ * 3) {
        int dk = idx % 3;
        int h  = (idx / 3) % H_;
        int c  = idx / (3 * H_);
        wt[(long)dk * C1_ * H_ + (long)c * H_ + h] = w[idx];
    }
}

// ---------- conv1 via 128x128 f32x2 tiles: relu(conv(lstm_out)) -> [B,C1,T] ----------
__global__ __launch_bounds__(256)
void conv1_kernel(const float* __restrict__ X, const float* __restrict__ Wt,
                  const float* __restrict__ bias, float* __restrict__ Y)
{
    const int b  = blockIdx.z;
    const int t0 = blockIdx.y * 128, c0 = blockIdx.x * 128;
    __shared__ float As[16][128];
    __shared__ float Bs[16][128];
    const int tid = threadIdx.x;
    const int tx = tid & 15, ty = tid >> 4;
    const int lm = tid >> 1;
    const int lk = (tid & 1) * 8;

    float2 acc[4][8];
#pragma unroll
    for (int p = 0; p < 4; p++)
#pragma unroll
        for (int j = 0; j < 8; j++) acc[p][j] = make_float2(0.f, 0.f);

    for (int dk = 0; dk < 3; dk++) {
        const float* Wd = Wt + (long)dk * C1_ * H_;
        for (int k0 = 0; k0 < H_; k0 += 16) {
            {
                int t = t0 + lm + dk - 1;
                float4 a0 = make_float4(0.f, 0.f, 0.f, 0.f), a1 = a0;
                if (t >= 0 && t < T_) {
                    const float* ap = &X[((long)b * T_ + t) * H_ + k0 + lk];
                    a0 = *(const float4*)ap;
                    a1 = *(const float4*)(ap + 4);
                }
                As[lk + 0][lm] = a0.x; As[lk + 1][lm] = a0.y;
                As[lk + 2][lm] = a0.z; As[lk + 3][lm] = a0.w;
                As[lk + 4][lm] = a1.x; As[lk + 5][lm] = a1.y;
                As[lk + 6][lm] = a1.z; As[lk + 7][lm] = a1.w;
            }
            {
                const float* bp = &Wd[(long)(c0 + lm) * H_ + k0 + lk];
                float4 b0 = *(const float4*)bp;
                float4 b1 = *(const float4*)(bp + 4);
                Bs[lk + 0][lm] = b0.x; Bs[lk + 1][lm] = b0.y;
                Bs[lk + 2][lm] = b0.z; Bs[lk + 3][lm] = b0.w;
                Bs[lk + 4][lm] = b1.x; Bs[lk + 5][lm] = b1.y;
                Bs[lk + 6][lm] = b1.z; Bs[lk + 7][lm] = b1.w;
            }
            __syncthreads();
#pragma unroll
            for (int kk = 0; kk < 16; kk++) {
                float4 av0 = *(const float4*)&As[kk][ty * 8];
                float4 av1 = *(const float4*)&As[kk][ty * 8 + 4];
                float2 a2[4] = { make_float2(av0.x, av0.y), make_float2(av0.z, av0.w),
                                 make_float2(av1.x, av1.y), make_float2(av1.z, av1.w) };
                float4 bv0 = *(const float4*)&Bs[kk][tx * 8];
                float4 bv1 = *(const float4*)&Bs[kk][tx * 8 + 4];
                float bj[8] = { bv0.x, bv0.y, bv0.z, bv0.w, bv1.x, bv1.y, bv1.z, bv1.w };
#pragma unroll
                for (int j = 0; j < 8; j++) {
                    float2 b2 = make_float2(bj[j], bj[j]);
#pragma unroll
                    for (int p = 0; p < 4; p++) acc[p][j] = ffma2(a2[p], b2, acc[p][j]);
                }
            }
            __syncthreads();
        }
    }
#pragma unroll
    for (int j = 0; j < 8; j++) {
        int c = c0 + tx * 8 + j;
        float bvv = bias[c];
        float* yrow = &Y[((long)b * C1_ + c) * T_];
#pragma unroll
        for (int p = 0; p < 4; p++) {
            int t = t0 + ty * 8 + 2 * p;
            float v0 = acc[p][j].x + bvv;
            float v1 = acc[p][j].y + bvv;
            yrow[t]     = v0 > 0.f ? v0 : 0.f;
            yrow[t + 1] = v1 > 0.f ? v1 : 0.f;
        }
    }
}

// ---------- conv2: [B,C1,T] -> [B,2,T] ----------
__global__ void conv2_kernel(const float* __restrict__ A1, const float* __restrict__ W2,
                             const float* __restrict__ b2, float* __restrict__ A2)
{
    int b = blockIdx.y;
    int t = blockIdx.x * blockDim.x + threadIdx.x;
    float acc0 = b2[0], acc1 = b2[1];
    const float* base = A1 + (long)b * C1_ * T_;
    for (int c = 0; c < C1_; c++) {
        const float* row = base + (long)c * T_;
        float xm = (t >= 1)      ? row[t - 1] : 0.f;
        float x0 = row[t];
        float xp = (t <= T_ - 2) ? row[t + 1] : 0.f;
        const float* w0 = W2 + c * 3;
        const float* w1 = W2 + (C1_ + c) * 3;
        acc0 += xm * w0[0] + x0 * w0[1] + xp * w0[2];
        acc1 += xm * w1[0] + x0 * w1[1] + xp * w1[2];
    }
    A2[((long)b * 2 + 0) * T_ + t] = acc0;
    A2[((long)b * 2 + 1) * T_ + t] = acc1;
}

static float* sym(const void* s)
{
    void* p = nullptr;
    cudaGetSymbolAddress(&p, (const void*)s);
    return (float*)p;
}

extern "C" void kernel_launch(void* const* d_in, const int* in_sizes, int n_in,
                              void* d_out, int out_size)
{
    const float* x     = (const float*)d_in[0];
    const float* w_in1 = (const float*)d_in[1];
    const float* b_in1 = (const float*)d_in[2];
    const float* w_in2 = (const float*)d_in[3];
    const float* b_in2 = (const float*)d_in[4];
    const float* w_q   = (const float*)d_in[5];
    const float* b_q   = (const float*)d_in[6];
    const float* w_k   = (const float*)d_in[7];
    const float* b_k   = (const float*)d_in[8];
    const float* w_v   = (const float*)d_in[9];
    const float* b_v   = (const float*)d_in[10];
    const float* w_p   = (const float*)d_in[11];
    const float* b_p   = (const float*)d_in[12];
    const float* ln_g  = (const float*)d_in[13];
    const float* ln_b  = (const float*)d_in[14];
    const float* w_ih  = (const float*)d_in[15];
    const float* w_hh  = (const float*)d_in[16];
    const float* b_ih  = (const float*)d_in[17];
    const float* b_hh  = (const float*)d_in[18];
    const float* w_c1  = (const float*)d_in[19];
    const float* b_c1  = (const float*)d_in[20];
    const float* w_c2  = (const float*)d_in[21];
    const float* b_c2  = (const float*)d_in[22];
    float* out = (float*)d_out;

    float* h1   = sym(g_h1);
    float* hh   = sym(g_hh);
    float* q    = sym(g_q);
    float* k    = sym(g_k);
    float* v    = sym(g_v);
    float* sc   = sym(g_sc);
    float* o    = sym(g_o);
    float* y    = sym(g_y);
    float* gx   = sym(g_gx);
    float* lstm = sym(g_lstm);
    float* hbuf = sym(g_hbuf);
    float* a1   = sym(g_a1);
    float* a2   = sym(g_a2);
    float* wc1t = sym(g_wc1t);

    dim3 blk(256);

    // in_pro: 1x1 -> leaky -> 1x1
    gemm128<1,1,1><<<dim3(4,64,1), blk>>>(x, w_in1, b_in1, h1,
        BT_, E_, E_, E_, E_, E_, 1, 0,0,0,0,0,0);
    gemm128<0,1,1><<<dim3(4,64,1), blk>>>(h1, w_in2, b_in2, hh,
        BT_, E_, E_, E_, E_, E_, 1, 0,0,0,0,0,0);

    // QKV
    gemm128<0,1,1><<<dim3(8,64,1), blk>>>(hh, w_q, b_q, q,
        BT_, NH_*QD_, E_, E_, E_, NH_*QD_, 1, 0,0,0,0,0,0);
    gemm128<0,1,1><<<dim3(8,64,1), blk>>>(hh, w_k, b_k, k,
        BT_, NH_*QD_, E_, E_, E_, NH_*QD_, 1, 0,0,0,0,0,0);
    gemm128<0,1,1><<<dim3(16,64,1), blk>>>(hh, w_v, b_v, v,
        BT_, NH_*VD_, E_, E_, E_, NH_*VD_, 1, 0,0,0,0,0,0);

    // scores = q @ k^T per (b, head)
    gemm128<0,1,0><<<dim3(8,8,B_*NH_), blk>>>(q, k, nullptr, sc,
        T_, T_, QD_, NH_*QD_, NH_*QD_, T_, NH_,
        (long)T_*NH_*QD_, (long)QD_, (long)T_*NH_*QD_, (long)QD_,
        (long)NH_*T_*T_, (long)T_*T_);

    softmax_kernel<<<B_*NH_*T_, 256>>>(sc);

    // o = attn @ v per (b, head)
    gemm128<0,0,0><<<dim3(4,8,B_*NH_), blk>>>(sc, v, nullptr, o,
        T_, VD_, T_, T_, NH_*VD_, NH_*VD_, NH_,
        (long)NH_*T_*T_, (long)T_*T_, (long)T_*NH_*VD_, (long)VD_,
        (long)T_*NH_*VD_, (long)VD_);

    // out projection + layernorm
    gemm128<0,1,1><<<dim3(4,64,1), blk>>>(o, w_p, b_p, y,
        BT_, E_, NH_*VD_, NH_*VD_, NH_*VD_, E_, 1, 0,0,0,0,0,0);
    layernorm_kernel<<<BT_, 128>>>(y, ln_g, ln_b, y);

    // LSTM input GEMM: gx = y @ w_ih^T + b_ih
    gemm128<0,1,1><<<dim3(32,64,1), blk>>>(y, w_ih, b_ih, gx,
        BT_, G4_, E_, E_, E_, G4_, 1, 0,0,0,0,0,0);

    reset_kernel<<<64, 256>>>();
    lstm_kernel<<<LSTM_NB, 256>>>(gx, w_hh, b_hh, hbuf, lstm);

    // conv pooling
    repack_wc1<<<(C1_*H_*3 + 255)/256, 256>>>(w_c1, wc1t);
    conv1_kernel<<<dim3(4,8,B_), blk>>>(lstm, wc1t, b_c1, a1);
    conv2_kernel<<<dim3(4,B_), 256>>>(a1, w_c2, b_c2, a2);
    softmax_kernel<<<B_*C2_, 256>>>(a2);

    // feat = a2 @ lstm_out : [2,1024]@[1024,1024] per batch -> out [8,2048]
    gemm_kernel<0,0,0><<<dim3(16,1,B_), blk>>>(a2, lstm, nullptr, out,
        C2_, H_, T_, T_, H_, H_, 1,
        (long)C2_*T_, 0, (long)T_*H_, 0, (long)C2_*H_, 0);
}

// round 8
// speedup vs baseline: 1.3511x; 1.1829x over previous
#include <cuda_runtime.h>

#define B_   8
#define T_   1024
#define E_   512
#define H_   1024
#define NH_  4
#define QD_  256
#define VD_  512
#define C1_  512
#define C2_  2
#define BT_  (B_ * T_)
#define G4_  (4 * H_)

__device__ float g_h1[(size_t)BT_ * E_];
__device__ float g_hh[(size_t)BT_ * E_];
__device__ float g_q [(size_t)BT_ * (NH_ * QD_)];
__device__ float g_k [(size_t)BT_ * (NH_ * QD_)];
__device__ float g_v [(size_t)BT_ * (NH_ * VD_)];
__device__ float g_sc[(size_t)B_ * NH_ * T_ * T_];
__device__ float g_o [(size_t)BT_ * (NH_ * VD_)];
__device__ float g_y [(size_t)BT_ * E_];
__device__ float g_gx[(size_t)BT_ * G4_];
__device__ float g_lstm[(size_t)BT_ * H_];
__device__ float g_hbuf[2 * B_ * H_];
__device__ float g_a1[(size_t)B_ * C1_ * T_];
__device__ float g_a2[(size_t)B_ * C2_ * T_];
__device__ float g_wc1t[(size_t)3 * C1_ * H_];
__device__ unsigned g_bar;

__device__ __forceinline__ float2 ffma2(float2 a, float2 b, float2 c)
{
    unsigned long long A = *reinterpret_cast<unsigned long long*>(&a);
    unsigned long long Bb = *reinterpret_cast<unsigned long long*>(&b);
    unsigned long long Cc = *reinterpret_cast<unsigned long long*>(&c);
    unsigned long long D;
    asm("fma.rn.f32x2 %0, %1, %2, %3;" : "=l"(D) : "l"(A), "l"(Bb), "l"(Cc));
    return *reinterpret_cast<float2*>(&D);
}

// ========== 128x128 SGEMM, f32x2 FMA, split-column micro-tile ==========
// C = act(A @ op(B) + bias). A:[M,K] row-major. TRANSB=1: B:[N,K]; 0: B:[K,N].
// Requires: M%128==0, N%128==0, K%16==0.
// Thread (tx,ty) computes rows m0+ty*8..+7, cols {n0+tx*4..+3} u {n0+64+tx*4..+3}.
template<int ACT, int TRANSB, int HASBIAS>
__global__ __launch_bounds__(256)
void gemm128(const float* __restrict__ A, const float* __restrict__ Bm,
             const float* __restrict__ bias, float* __restrict__ C,
             int M, int N, int Kd, int lda, int ldb, int ldc,
             int bInner, long sAo, long sAi, long sBo, long sBi,
             long sCo, long sCi)
{
    int z  = blockIdx.z;
    int zo = z / bInner, zi = z % bInner;
    A  += zo * sAo + zi * sAi;
    Bm += zo * sBo + zi * sBi;
    C  += zo * sCo + zi * sCi;

    __shared__ float As[16][128];
    __shared__ float Bs[16][128];

    const int tid = threadIdx.x;
    const int tx = tid & 15, ty = tid >> 4;
    const int m0 = blockIdx.y * 128, n0 = blockIdx.x * 128;
    const int lm = tid >> 1;           // 0..127
    const int lk = (tid & 1) * 8;      // 0 / 8
    const int br = tid >> 4;           // TRANSB=0: k-row 0..15
    const int bc = (tid & 15) * 8;     // TRANSB=0: n-col

    float2 acc[4][8];
#pragma unroll
    for (int p = 0; p < 4; p++)
#pragma unroll
        for (int j = 0; j < 8; j++) acc[p][j] = make_float2(0.f, 0.f);

    for (int k0 = 0; k0 < Kd; k0 += 16) {
        {
            const float* p = &A[(long)(m0 + lm) * lda + k0 + lk];
            float4 v0 = *(const float4*)p, v1 = *(const float4*)(p + 4);
            As[lk + 0][lm] = v0.x; As[lk + 1][lm] = v0.y;
            As[lk + 2][lm] = v0.z; As[lk + 3][lm] = v0.w;
            As[lk + 4][lm] = v1.x; As[lk + 5][lm] = v1.y;
            As[lk + 6][lm] = v1.z; As[lk + 7][lm] = v1.w;
        }
        if (TRANSB) {
            const float* p = &Bm[(long)(n0 + lm) * ldb + k0 + lk];
            float4 v0 = *(const float4*)p, v1 = *(const float4*)(p + 4);
            Bs[lk + 0][lm] = v0.x; Bs[lk + 1][lm] = v0.y;
            Bs[lk + 2][lm] = v0.z; Bs[lk + 3][lm] = v0.w;
            Bs[lk + 4][lm] = v1.x; Bs[lk + 5][lm] = v1.y;
            Bs[lk + 6][lm] = v1.z; Bs[lk + 7][lm] = v1.w;
        } else {
            const float* p = &Bm[(long)(k0 + br) * ldb + n0 + bc];
            float4 v0 = *(const float4*)p, v1 = *(const float4*)(p + 4);
            *(float4*)&Bs[br][bc]     = v0;
            *(float4*)&Bs[br][bc + 4] = v1;
        }
        __syncthreads();
#pragma unroll
        for (int kk = 0; kk < 16; kk++) {
            float4 av0 = *(const float4*)&As[kk][ty * 8];
            float4 av1 = *(const float4*)&As[kk][ty * 8 + 4];
            float2 a2[4] = { make_float2(av0.x, av0.y), make_float2(av0.z, av0.w),
                             make_float2(av1.x, av1.y), make_float2(av1.z, av1.w) };
            float4 bv0 = *(const float4*)&Bs[kk][tx * 4];
            float4 bv1 = *(const float4*)&Bs[kk][64 + tx * 4];
            float bj[8] = { bv0.x, bv0.y, bv0.z, bv0.w, bv1.x, bv1.y, bv1.z, bv1.w };
#pragma unroll
            for (int j = 0; j < 8; j++) {
                float2 b2 = make_float2(bj[j], bj[j]);
#pragma unroll
                for (int p = 0; p < 4; p++) acc[p][j] = ffma2(a2[p], b2, acc[p][j]);
            }
        }
        __syncthreads();
    }

    const int nlo = n0 + tx * 4;
    const int nhi = n0 + 64 + tx * 4;
    float bb[8];
#pragma unroll
    for (int j = 0; j < 4; j++) bb[j] = HASBIAS ? bias[nlo + j] : 0.f;
#pragma unroll
    for (int j = 4; j < 8; j++) bb[j] = HASBIAS ? bias[nhi + j - 4] : 0.f;
#pragma unroll
    for (int p = 0; p < 4; p++) {
        int m = m0 + ty * 8 + 2 * p;
        float r0[8], r1[8];
#pragma unroll
        for (int j = 0; j < 8; j++) {
            float v0 = acc[p][j].x + bb[j];
            float v1 = acc[p][j].y + bb[j];
            if (ACT == 1) { v0 = v0 >= 0.f ? v0 : 0.25f * v0; v1 = v1 >= 0.f ? v1 : 0.25f * v1; }
            r0[j] = v0; r1[j] = v1;
        }
        *(float4*)&C[(long)m * ldc + nlo]       = make_float4(r0[0], r0[1], r0[2], r0[3]);
        *(float4*)&C[(long)m * ldc + nhi]       = make_float4(r0[4], r0[5], r0[6], r0[7]);
        *(float4*)&C[(long)(m + 1) * ldc + nlo] = make_float4(r1[0], r1[1], r1[2], r1[3]);
        *(float4*)&C[(long)(m + 1) * ldc + nhi] = make_float4(r1[4], r1[5], r1[6], r1[7]);
    }
}

// ---------- old 64x64 SGEMM kept only for the tiny final pooling GEMM ----------
template<int ACT, int TRANSB, int HASBIAS>
__global__ __launch_bounds__(256)
void gemm_kernel(const float* __restrict__ A, const float* __restrict__ Bm,
                 const float* __restrict__ bias, float* __restrict__ C,
                 int M, int N, int Kd, int lda, int ldb, int ldc,
                 int bInner, long sAo, long sAi, long sBo, long sBi,
                 long sCo, long sCi)
{
    int z  = blockIdx.z;
    int zo = z / bInner, zi = z % bInner;
    A  += zo * sAo + zi * sAi;
    Bm += zo * sBo + zi * sBi;
    C  += zo * sCo + zi * sCi;

    __shared__ float As[16][64];
    __shared__ float Bs[16][64];

    int tid = threadIdx.x;
    int tx = tid & 15, ty = tid >> 4;
    int m0 = blockIdx.y * 64, n0 = blockIdx.x * 64;
    int arow = tid >> 2, akq = (tid & 3) * 4;

    float acc[4][4];
#pragma unroll
    for (int i = 0; i < 4; i++)
#pragma unroll
        for (int j = 0; j < 4; j++) acc[i][j] = 0.f;

    for (int k0 = 0; k0 < Kd; k0 += 16) {
        {
            int m = m0 + arow;
            float4 v = make_float4(0.f, 0.f, 0.f, 0.f);
            if (m < M) v = *(const float4*)&A[(long)m * lda + k0 + akq];
            As[akq + 0][arow] = v.x; As[akq + 1][arow] = v.y;
            As[akq + 2][arow] = v.z; As[akq + 3][arow] = v.w;
        }
        if (TRANSB) {
            int nn = n0 + arow;
            float4 v = make_float4(0.f, 0.f, 0.f, 0.f);
            if (nn < N) v = *(const float4*)&Bm[(long)nn * ldb + k0 + akq];
            Bs[akq + 0][arow] = v.x; Bs[akq + 1][arow] = v.y;
            Bs[akq + 2][arow] = v.z; Bs[akq + 3][arow] = v.w;
        } else {
#pragma unroll
            for (int p = 0; p < 4; p++) {
                int kk = (tid >> 6) + p * 4;
                int nn = n0 + (tid & 63);
                float v = 0.f;
                if (nn < N) v = Bm[(long)(k0 + kk) * ldb + nn];
                Bs[kk][tid & 63] = v;
            }
        }
        __syncthreads();
#pragma unroll
        for (int kk = 0; kk < 16; kk++) {
            float4 av = *(const float4*)&As[kk][ty * 4];
            float4 bv = *(const float4*)&Bs[kk][tx * 4];
            float a[4] = {av.x, av.y, av.z, av.w};
            float b[4] = {bv.x, bv.y, bv.z, bv.w};
#pragma unroll
            for (int i = 0; i < 4; i++)
#pragma unroll
                for (int j = 0; j < 4; j++) acc[i][j] += a[i] * b[j];
        }
        __syncthreads();
    }
#pragma unroll
    for (int i = 0; i < 4; i++) {
        int m = m0 + ty * 4 + i;
        if (m >= M) continue;
#pragma unroll
        for (int j = 0; j < 4; j++) {
            int nn = n0 + tx * 4 + j;
            if (nn >= N) continue;
            float v = acc[i][j];
            if (HASBIAS) v += bias[nn];
            if (ACT == 1) v = v >= 0.f ? v : 0.25f * v;
            C[(long)m * ldc + nn] = v;
        }
    }
}

// ---------- softmax over rows of 1024 (in place), 256 threads ----------
__global__ void softmax_kernel(float* __restrict__ data)
{
    long row = blockIdx.x;
    float4* p = (float4*)(data + row * 1024);
    float4 v = p[threadIdx.x];
    int lane = threadIdx.x & 31, w = threadIdx.x >> 5;
    __shared__ float sm[8], ss[8];

    float m = fmaxf(fmaxf(v.x, v.y), fmaxf(v.z, v.w));
#pragma unroll
    for (int o = 16; o; o >>= 1) m = fmaxf(m, __shfl_xor_sync(0xffffffffu, m, o));
    if (lane == 0) sm[w] = m;
    __syncthreads();
    float bm = sm[0];
#pragma unroll
    for (int i = 1; i < 8; i++) bm = fmaxf(bm, sm[i]);

    v.x = __expf(v.x - bm); v.y = __expf(v.y - bm);
    v.z = __expf(v.z - bm); v.w = __expf(v.w - bm);
    float s = v.x + v.y + v.z + v.w;
#pragma unroll
    for (int o = 16; o; o >>= 1) s += __shfl_xor_sync(0xffffffffu, s, o);
    if (lane == 0) ss[w] = s;
    __syncthreads();
    float bs = ss[0] + ss[1] + ss[2] + ss[3] + ss[4] + ss[5] + ss[6] + ss[7];
    float inv = 1.f / bs;
    v.x *= inv; v.y *= inv; v.z *= inv; v.w *= inv;
    p[threadIdx.x] = v;
}

// ---------- LayerNorm over E=512, 128 threads ----------
__global__ void layernorm_kernel(const float* __restrict__ x, const float* __restrict__ g,
                                 const float* __restrict__ bta, float* __restrict__ y)
{
    long row = blockIdx.x;
    const float4* xr = (const float4*)(x + row * 512);
    float4 v = xr[threadIdx.x];
    int lane = threadIdx.x & 31, w = threadIdx.x >> 5;
    float s1 = v.x + v.y + v.z + v.w;
    float s2 = v.x * v.x + v.y * v.y + v.z * v.z + v.w * v.w;
#pragma unroll
    for (int o = 16; o; o >>= 1) {
        s1 += __shfl_xor_sync(0xffffffffu, s1, o);
        s2 += __shfl_xor_sync(0xffffffffu, s2, o);
    }
    __shared__ float a1s[4], a2s[4];
    if (lane == 0) { a1s[w] = s1; a2s[w] = s2; }
    __syncthreads();
    s1 = a1s[0] + a1s[1] + a1s[2] + a1s[3];
    s2 = a2s[0] + a2s[1] + a2s[2] + a2s[3];
    float mean = s1 * (1.f / 512.f);
    float var  = s2 * (1.f / 512.f) - mean * mean;
    float inv  = rsqrtf(var + 1e-5f);
    float4 gv = ((const float4*)g)[threadIdx.x];
    float4 bv = ((const float4*)bta)[threadIdx.x];
    float4 o4;
    o4.x = (v.x - mean) * inv * gv.x + bv.x;
    o4.y = (v.y - mean) * inv * gv.y + bv.y;
    o4.z = (v.z - mean) * inv * gv.z + bv.z;
    o4.w = (v.w - mean) * inv * gv.w + bv.w;
    ((float4*)(y + row * 512))[threadIdx.x] = o4;
}

__global__ void reset_kernel()
{
    int i = blockIdx.x * blockDim.x + threadIdx.x;
    if (i < 2 * B_ * H_) g_hbuf[i] = 0.f;
    if (i == 0) g_bar = 0u;
}

__device__ __forceinline__ float fsigmoid(float x) { return 1.f / (1.f + __expf(-x)); }
__device__ __forceinline__ float ftanh(float x)
{
    float e = __expf(2.f * x);
    return 1.f - 2.f / (e + 1.f);
}

#define LSTM_NB 128
__global__ __launch_bounds__(256, 1)
void lstm_kernel(const float* __restrict__ gx, const float* __restrict__ Whh,
                 const float* __restrict__ bhh, float* __restrict__ hbuf,
                 float* __restrict__ lstm_out)
{
    const int tid  = threadIdx.x;
    const int lane = tid & 31;
    const int w    = tid >> 5;
    const int bi   = blockIdx.x;

    __shared__ float sh[8][1024];
    __shared__ float sg[32][8];
    __shared__ float scs[8][8];

    float2 wreg[4][16];
#pragma unroll
    for (int r = 0; r < 4; r++) {
        int lr = w * 4 + r;
        int j  = (lr >> 3) * H_ + bi * 8 + (lr & 7);
        const float2* wrow = (const float2*)(Whh + (long)j * H_);
#pragma unroll
        for (int kk = 0; kk < 16; kk++) wreg[r][kk] = wrow[kk * 32 + lane];
    }

    // bit-reversed output index for the multi-value butterfly reduction
    const int oidx = ((lane & 1) << 3) | ((lane & 2) << 1) | ((lane & 4) >> 1) | ((lane & 8) >> 3);
    const int o_r = oidx >> 2, o_b = oidx & 3;

    int ul = tid >> 3, bb = tid & 7;
    int u  = bi * 8 + ul;
    float rb0 = 0.f, rb1 = 0.f, rb2 = 0.f, rb3 = 0.f;
    if (tid < 64) {
        rb0 = bhh[0 * H_ + u]; rb1 = bhh[1 * H_ + u];
        rb2 = bhh[2 * H_ + u]; rb3 = bhh[3 * H_ + u];
        scs[ul][bb] = 0.f;
    }

    unsigned target = 0;
    for (int t = 0; t < T_; t++) {
        float px0, px1, px2, px3;
        if (tid < 64) {
            long grow = ((long)bb * T_ + t) * G4_;
            px0 = gx[grow + 0 * H_ + u];
            px1 = gx[grow + 1 * H_ + u];
            px2 = gx[grow + 2 * H_ + u];
            px3 = gx[grow + 3 * H_ + u];
        }

        const float4* hr = (const float4*)(hbuf + (t & 1) * (B_ * H_));
        float*        hw =                 hbuf + ((t + 1) & 1) * (B_ * H_);
#pragma unroll
        for (int p = 0; p < 8; p++)
            ((float4*)&sh[0][0])[tid + p * 256] = hr[tid + p * 256];
        __syncthreads();

#pragma unroll
        for (int bh = 0; bh < 2; bh++) {
            float2 acc[4][4];
#pragma unroll
            for (int r = 0; r < 4; r++)
#pragma unroll
                for (int b = 0; b < 4; b++) acc[r][b] = make_float2(0.f, 0.f);
#pragma unroll
            for (int kk = 0; kk < 16; kk++) {
                float2 h2[4];
#pragma unroll
                for (int b = 0; b < 4; b++)
                    h2[b] = *(const float2*)&sh[bh * 4 + b][kk * 64 + lane * 2];
#pragma unroll
                for (int r = 0; r < 4; r++) {
                    float2 wv = wreg[r][kk];
#pragma unroll
                    for (int b = 0; b < 4; b++) acc[r][b] = ffma2(wv, h2[b], acc[r][b]);
                }
            }
            // multi-value butterfly: 16 outputs reduced across 32 lanes in 17 shfl
            float vals[16];
#pragma unroll
            for (int r = 0; r < 4; r++)
#pragma unroll
                for (int b = 0; b < 4; b++) vals[r * 4 + b] = acc[r][b].x + acc[r][b].y;
            int cnt = 16;
#pragma unroll
            for (int d = 1; d <= 8; d <<= 1) {
                int half = cnt >> 1;
                bool up = (lane & d) != 0;
#pragma unroll
                for (int i = 0; i < 8; i++) {
                    if (i >= half) break;
                    float send = up ? vals[i] : vals[i + half];
                    float keep = up ? vals[i + half] : vals[i];
                    float recv = __shfl_xor_sync(0xffffffffu, send, d);
                    vals[i] = keep + recv;
                }
                cnt = half;
            }
            vals[0] += __shfl_xor_sync(0xffffffffu, vals[0], 16);
            if (lane < 16) sg[w * 4 + o_r][bh * 4 + o_b] = vals[0];
        }
        __syncthreads();

        if (tid < 64) {
            float gi = sg[0 * 8 + ul][bb] + px0 + rb0;
            float gf = sg[1 * 8 + ul][bb] + px1 + rb1;
            float gg = sg[2 * 8 + ul][bb] + px2 + rb2;
            float go = sg[3 * 8 + ul][bb] + px3 + rb3;
            float c  = fsigmoid(gf) * scs[ul][bb] + fsigmoid(gi) * ftanh(gg);
            float hn = fsigmoid(go) * ftanh(c);
            scs[ul][bb] = c;
            hw[bb * H_ + u] = hn;
            lstm_out[((long)bb * T_ + t) * H_ + u] = hn;
        }
        __syncthreads();

        target += LSTM_NB;
        if (tid == 0) {
            asm volatile("fence.acq_rel.gpu;" ::: "memory");
            atomicAdd(&g_bar, 1u);
            unsigned r;
            do {
                asm volatile("ld.global.acquire.gpu.u32 %0, [%1];"
                             : "=r"(r) : "l"(&g_bar));
            } while (r < target);
        }
        __syncthreads();
    }
}

// ---------- conv weight repack: w[c][h][dk] -> wt[dk][c][h] ----------
__global__ void repack_wc1(const float* __restrict__ w, float* __restrict__ wt)
{
    int idx = blockIdx.x * blockDim.x + threadIdx.x;
    if (idx < C1_ * H_ * 3) {
        int dk = idx % 3;
        int h  = (idx / 3) % H_;
        int c  = idx / (3 * H_);
        wt[(long)dk * C1_ * H_ + (long)c * H_ + h] = w[idx];
    }
}

// ---------- conv1 via 128x128 f32x2 tiles (split-column): relu(conv) -> [B,C1,T] ----------
__global__ __launch_bounds__(256)
void conv1_kernel(const float* __restrict__ X, const float* __restrict__ Wt,
                  const float* __restrict__ bias, float* __restrict__ Y)
{
    const int b  = blockIdx.z;
    const int t0 = blockIdx.y * 128, c0 = blockIdx.x * 128;
    __shared__ float As[16][128];
    __shared__ float Bs[16][128];
    const int tid = threadIdx.x;
    const int tx = tid & 15, ty = tid >> 4;
    const int lm = tid >> 1;
    const int lk = (tid & 1) * 8;

    float2 acc[4][8];
#pragma unroll
    for (int p = 0; p < 4; p++)
#pragma unroll
        for (int j = 0; j < 8; j++) acc[p][j] = make_float2(0.f, 0.f);

    for (int dk = 0; dk < 3; dk++) {
        const float* Wd = Wt + (long)dk * C1_ * H_;
        for (int k0 = 0; k0 < H_; k0 += 16) {
            {
                int t = t0 + lm + dk - 1;
                float4 a0 = make_float4(0.f, 0.f, 0.f, 0.f), a1 = a0;
                if (t >= 0 && t < T_) {
                    const float* ap = &X[((long)b * T_ + t) * H_ + k0 + lk];
                    a0 = *(const float4*)ap;
                    a1 = *(const float4*)(ap + 4);
                }
                As[lk + 0][lm] = a0.x; As[lk + 1][lm] = a0.y;
                As[lk + 2][lm] = a0.z; As[lk + 3][lm] = a0.w;
                As[lk + 4][lm] = a1.x; As[lk + 5][lm] = a1.y;
                As[lk + 6][lm] = a1.z; As[lk + 7][lm] = a1.w;
            }
            {
                const float* bp = &Wd[(long)(c0 + lm) * H_ + k0 + lk];
                float4 b0 = *(const float4*)bp;
                float4 b1 = *(const float4*)(bp + 4);
                Bs[lk + 0][lm] = b0.x; Bs[lk + 1][lm] = b0.y;
                Bs[lk + 2][lm] = b0.z; Bs[lk + 3][lm] = b0.w;
                Bs[lk + 4][lm] = b1.x; Bs[lk + 5][lm] = b1.y;
                Bs[lk + 6][lm] = b1.z; Bs[lk + 7][lm] = b1.w;
            }
            __syncthreads();
#pragma unroll
            for (int kk = 0; kk < 16; kk++) {
                float4 av0 = *(const float4*)&As[kk][ty * 8];
                float4 av1 = *(const float4*)&As[kk][ty * 8 + 4];
                float2 a2[4] = { make_float2(av0.x, av0.y), make_float2(av0.z, av0.w),
                                 make_float2(av1.x, av1.y), make_float2(av1.z, av1.w) };
                float4 bv0 = *(const float4*)&Bs[kk][tx * 4];
                float4 bv1 = *(const float4*)&Bs[kk][64 + tx * 4];
                float bj[8] = { bv0.x, bv0.y, bv0.z, bv0.w, bv1.x, bv1.y, bv1.z, bv1.w };
#pragma unroll
                for (int j = 0; j < 8; j++) {
                    float2 b2 = make_float2(bj[j], bj[j]);
#pragma unroll
                    for (int p = 0; p < 4; p++) acc[p][j] = ffma2(a2[p], b2, acc[p][j]);
                }
            }
            __syncthreads();
        }
    }
#pragma unroll
    for (int j = 0; j < 8; j++) {
        int c = c0 + (j < 4 ? tx * 4 + j : 64 + tx * 4 + (j - 4));
        float bvv = bias[c];
        float* yrow = &Y[((long)b * C1_ + c) * T_];
#pragma unroll
        for (int p = 0; p < 4; p++) {
            int t = t0 + ty * 8 + 2 * p;
            float v0 = acc[p][j].x + bvv;
            float v1 = acc[p][j].y + bvv;
            yrow[t]     = v0 > 0.f ? v0 : 0.f;
            yrow[t + 1] = v1 > 0.f ? v1 : 0.f;
        }
    }
}

// ---------- conv2: [B,C1,T] -> [B,2,T] ----------
__global__ void conv2_kernel(const float* __restrict__ A1, const float* __restrict__ W2,
                             const float* __restrict__ b2, float* __restrict__ A2)
{
    int b = blockIdx.y;
    int t = blockIdx.x * blockDim.x + threadIdx.x;
    float acc0 = b2[0], acc1 = b2[1];
    const float* base = A1 + (long)b * C1_ * T_;
    for (int c = 0; c < C1_; c++) {
        const float* row = base + (long)c * T_;
        float xm = (t >= 1)      ? row[t - 1] : 0.f;
        float x0 = row[t];
        float xp = (t <= T_ - 2) ? row[t + 1] : 0.f;
        const float* w0 = W2 + c * 3;
        const float* w1 = W2 + (C1_ + c) * 3;
        acc0 += xm * w0[0] + x0 * w0[1] + xp * w0[2];
        acc1 += xm * w1[0] + x0 * w1[1] + xp * w1[2];
    }
    A2[((long)b * 2 + 0) * T_ + t] = acc0;
    A2[((long)b * 2 + 1) * T_ + t] = acc1;
}

static float* sym(const void* s)
{
    void* p = nullptr;
    cudaGetSymbolAddress(&p, (const void*)s);
    return (float*)p;
}

extern "C" void kernel_launch(void* const* d_in, const int* in_sizes, int n_in,
                              void* d_out, int out_size)
{
    const float* x     = (const float*)d_in[0];
    const float* w_in1 = (const float*)d_in[1];
    const float* b_in1 = (const float*)d_in[2];
    const float* w_in2 = (const float*)d_in[3];
    const float* b_in2 = (const float*)d_in[4];
    const float* w_q   = (const float*)d_in[5];
    const float* b_q   = (const float*)d_in[6];
    const float* w_k   = (const float*)d_in[7];
    const float* b_k   = (const float*)d_in[8];
    const float* w_v   = (const float*)d_in[9];
    const float* b_v   = (const float*)d_in[10];
    const float* w_p   = (const float*)d_in[11];
    const float* b_p   = (const float*)d_in[12];
    const float* ln_g  = (const float*)d_in[13];
    const float* ln_b  = (const float*)d_in[14];
    const float* w_ih  = (const float*)d_in[15];
    const float* w_hh  = (const float*)d_in[16];
    const float* b_ih  = (const float*)d_in[17];
    const float* b_hh  = (const float*)d_in[18];
    const float* w_c1  = (const float*)d_in[19];
    const float* b_c1  = (const float*)d_in[20];
    const float* w_c2  = (const float*)d_in[21];
    const float* b_c2  = (const float*)d_in[22];
    float* out = (float*)d_out;

    float* h1   = sym(g_h1);
    float* hh   = sym(g_hh);
    float* q    = sym(g_q);
    float* k    = sym(g_k);
    float* v    = sym(g_v);
    float* sc   = sym(g_sc);
    float* o    = sym(g_o);
    float* y    = sym(g_y);
    float* gx   = sym(g_gx);
    float* lstm = sym(g_lstm);
    float* hbuf = sym(g_hbuf);
    float* a1   = sym(g_a1);
    float* a2   = sym(g_a2);
    float* wc1t = sym(g_wc1t);

    dim3 blk(256);

    // in_pro: 1x1 -> leaky -> 1x1
    gemm128<1,1,1><<<dim3(4,64,1), blk>>>(x, w_in1, b_in1, h1,
        BT_, E_, E_, E_, E_, E_, 1, 0,0,0,0,0,0);
    gemm128<0,1,1><<<dim3(4,64,1), blk>>>(h1, w_in2, b_in2, hh,
        BT_, E_, E_, E_, E_, E_, 1, 0,0,0,0,0,0);

    // QKV
    gemm128<0,1,1><<<dim3(8,64,1), blk>>>(hh, w_q, b_q, q,
        BT_, NH_*QD_, E_, E_, E_, NH_*QD_, 1, 0,0,0,0,0,0);
    gemm128<0,1,1><<<dim3(8,64,1), blk>>>(hh, w_k, b_k, k,
        BT_, NH_*QD_, E_, E_, E_, NH_*QD_, 1, 0,0,0,0,0,0);
    gemm128<0,1,1><<<dim3(16,64,1), blk>>>(hh, w_v, b_v, v,
        BT_, NH_*VD_, E_, E_, E_, NH_*VD_, 1, 0,0,0,0,0,0);

    // scores = q @ k^T per (b, head)
    gemm128<0,1,0><<<dim3(8,8,B_*NH_), blk>>>(q, k, nullptr, sc,
        T_, T_, QD_, NH_*QD_, NH_*QD_, T_, NH_,
        (long)T_*NH_*QD_, (long)QD_, (long)T_*NH_*QD_, (long)QD_,
        (long)NH_*T_*T_, (long)T_*T_);

    softmax_kernel<<<B_*NH_*T_, 256>>>(sc);

    // o = attn @ v per (b, head)
    gemm128<0,0,0><<<dim3(4,8,B_*NH_), blk>>>(sc, v, nullptr, o,
        T_, VD_, T_, T_, NH_*VD_, NH_*VD_, NH_,
        (long)NH_*T_*T_, (long)T_*T_, (long)T_*NH_*VD_, (long)VD_,
        (long)T_*NH_*VD_, (long)VD_);

    // out projection + layernorm
    gemm128<0,1,1><<<dim3(4,64,1), blk>>>(o, w_p, b_p, y,
        BT_, E_, NH_*VD_, NH_*VD_, NH_*VD_, E_, 1, 0,0,0,0,0,0);
    layernorm_kernel<<<BT_, 128>>>(y, ln_g, ln_b, y);

    // LSTM input GEMM: gx = y @ w_ih^T + b_ih
    gemm128<0,1,1><<<dim3(32,64,1), blk>>>(y, w_ih, b_ih, gx,
        BT_, G4_, E_, E_, E_, G4_, 1, 0,0,0,0,0,0);

    reset_kernel<<<64, 256>>>();
    lstm_kernel<<<LSTM_NB, 256>>>(gx, w_hh, b_hh, hbuf, lstm);

    // conv pooling
    repack_wc1<<<(C1_*H_*3 + 255)/256, 256>>>(w_c1, wc1t);
    conv1_kernel<<<dim3(4,8,B_), blk>>>(lstm, wc1t, b_c1, a1);
    conv2_kernel<<<dim3(4,B_), 256>>>(a1, w_c2, b_c2, a2);
    softmax_kernel<<<B_*C2_, 256>>>(a2);

    // feat = a2 @ lstm_out : [2,1024]@[1024,1024] per batch -> out [8,2048]
    gemm_kernel<0,0,0><<<dim3(16,1,B_), blk>>>(a2, lstm, nullptr, out,
        C2_, H_, T_, T_, H_, H_, 1,
        (long)C2_*T_, 0, (long)T_*H_, 0, (long)C2_*H_, 0);
}

// round 11
// speedup vs baseline: 1.6324x; 1.2082x over previous
#include <cuda_runtime.h>

#define B_   8
#define T_   1024
#define E_   512
#define H_   1024
#define NH_  4
#define QD_  256
#define VD_  512
#define C1_  512
#define C2_  2
#define BT_  (B_ * T_)
#define G4_  (4 * H_)

__device__ float g_h1[(size_t)BT_ * E_];
__device__ float g_hh[(size_t)BT_ * E_];
__device__ float g_q [(size_t)BT_ * (NH_ * QD_)];
__device__ float g_k [(size_t)BT_ * (NH_ * QD_)];
__device__ float g_v [(size_t)BT_ * (NH_ * VD_)];
__device__ float g_sc[(size_t)B_ * NH_ * T_ * T_];
__device__ float g_o [(size_t)BT_ * (NH_ * VD_)];
__device__ float g_y [(size_t)BT_ * E_];
__device__ float g_gx[(size_t)BT_ * G4_];
__device__ float g_lstm[(size_t)BT_ * H_];
__device__ float g_hbuf[2 * B_ * H_];
__device__ float g_a1[(size_t)B_ * C1_ * T_];
__device__ float g_a2[(size_t)B_ * C2_ * T_];
__device__ float g_wc1t[(size_t)3 * C1_ * H_];
__device__ unsigned g_bar;

__device__ __forceinline__ float2 ffma2(float2 a, float2 b, float2 c)
{
    unsigned long long A = *reinterpret_cast<unsigned long long*>(&a);
    unsigned long long Bb = *reinterpret_cast<unsigned long long*>(&b);
    unsigned long long Cc = *reinterpret_cast<unsigned long long*>(&c);
    unsigned long long D;
    asm("fma.rn.f32x2 %0, %1, %2, %3;" : "=l"(D) : "l"(A), "l"(Bb), "l"(Cc));
    return *reinterpret_cast<float2*>(&D);
}

__device__ __forceinline__ unsigned f2tf(float x)
{
    unsigned r;
    asm("cvt.rna.tf32.f32 %0, %1;" : "=r"(r) : "f"(x));
    return r;
}

#define MMA8(d, A0, A1, A2, A3, B0, B1) \
    asm("mma.sync.aligned.m16n8k8.row.col.f32.tf32.tf32.f32 " \
        "{%0,%1,%2,%3},{%4,%5,%6,%7},{%8,%9},{%0,%1,%2,%3};" \
        : "+f"(d.x), "+f"(d.y), "+f"(d.z), "+f"(d.w) \
        : "r"(A0), "r"(A1), "r"(A2), "r"(A3), "r"(B0), "r"(B1))

// ========== 128x128 TF32 tensor-core GEMM ==========
// C = act(A @ op(B) + bias). A:[M,K] row-major. TRANSB=1: B:[N,K]; 0: B:[K,N].
// Requires: M%128==0, N%128==0, K%16==0.
// Smem layout: k-permuted (col(k) = (k&3)*4 + (k>>2)) so LDS.128 at [row][tig*4]
// yields fragment elements for both k-steps of a 16-wide slab.
#define SPAD 20
template<int ACT, int TRANSB, int HASBIAS>
__global__ __launch_bounds__(256)
void gemm_tf32(const float* __restrict__ A, const float* __restrict__ Bm,
               const float* __restrict__ bias, float* __restrict__ C,
               int M, int N, int Kd, int lda, int ldb, int ldc,
               int bInner, long sAo, long sAi, long sBo, long sBi,
               long sCo, long sCi)
{
    int z  = blockIdx.z;
    int zo = z / bInner, zi = z % bInner;
    A  += zo * sAo + zi * sAi;
    Bm += zo * sBo + zi * sBi;
    C  += zo * sCo + zi * sCi;

    __shared__ __align__(16) unsigned As[2][128][SPAD];
    __shared__ __align__(16) unsigned Bs[2][128][SPAD];

    const int tid  = threadIdx.x;
    const int lane = tid & 31, wid = tid >> 5;
    const int gid  = lane >> 2, tig = lane & 3;
    const int wm0  = (wid & 1) * 64, wn0 = (wid >> 1) * 32;
    const int m0   = blockIdx.y * 128, n0 = blockIdx.x * 128;

    const int lr  = tid >> 1, lkh = (tid & 1) * 8;   // A, and B when TRANSB=1
    const int vk  = tid >> 4, vn  = (tid & 15) * 8;  // B when TRANSB=0

    float4 acc[4][4];
#pragma unroll
    for (int mf = 0; mf < 4; mf++)
#pragma unroll
        for (int nf = 0; nf < 4; nf++) acc[mf][nf] = make_float4(0.f, 0.f, 0.f, 0.f);

    float av[8], bv[8];

    // ---- load slab 0 ----
    {
        const float* p = &A[(long)(m0 + lr) * lda + lkh];
        float4 v0 = *(const float4*)p, v1 = *(const float4*)(p + 4);
        av[0]=v0.x; av[1]=v0.y; av[2]=v0.z; av[3]=v0.w;
        av[4]=v1.x; av[5]=v1.y; av[6]=v1.z; av[7]=v1.w;
        const float* q = TRANSB ? &Bm[(long)(n0 + lr) * ldb + lkh]
                                : &Bm[(long)vk * ldb + n0 + vn];
        float4 w0 = *(const float4*)q, w1 = *(const float4*)(q + 4);
        bv[0]=w0.x; bv[1]=w0.y; bv[2]=w0.z; bv[3]=w0.w;
        bv[4]=w1.x; bv[5]=w1.y; bv[6]=w1.z; bv[7]=w1.w;
    }
    // ---- store slab 0 into buffer 0 ----
#pragma unroll
    for (int e = 0; e < 8; e++) {
        int k = lkh + e;
        As[0][lr][((k & 3) << 2) | (k >> 2)] = f2tf(av[e]);
    }
    if (TRANSB) {
#pragma unroll
        for (int e = 0; e < 8; e++) {
            int k = lkh + e;
            Bs[0][lr][((k & 3) << 2) | (k >> 2)] = f2tf(bv[e]);
        }
    } else {
        int pc = ((vk & 3) << 2) | (vk >> 2);
#pragma unroll
        for (int e = 0; e < 8; e++) Bs[0][vn + e][pc] = f2tf(bv[e]);
    }
    __syncthreads();

    const int nst = Kd >> 4;
    for (int s = 0; s < nst; s++) {
        const int cur = s & 1;
        if (s + 1 < nst) {
            int k0 = (s + 1) << 4;
            const float* p = &A[(long)(m0 + lr) * lda + k0 + lkh];
            float4 v0 = *(const float4*)p, v1 = *(const float4*)(p + 4);
            av[0]=v0.x; av[1]=v0.y; av[2]=v0.z; av[3]=v0.w;
            av[4]=v1.x; av[5]=v1.y; av[6]=v1.z; av[7]=v1.w;
            const float* q = TRANSB ? &Bm[(long)(n0 + lr) * ldb + k0 + lkh]
                                    : &Bm[(long)(k0 + vk) * ldb + n0 + vn];
            float4 w0 = *(const float4*)q, w1 = *(const float4*)(q + 4);
            bv[0]=w0.x; bv[1]=w0.y; bv[2]=w0.z; bv[3]=w0.w;
            bv[4]=w1.x; bv[5]=w1.y; bv[6]=w1.z; bv[7]=w1.w;
        }

        uint4 afl[4], afh[4], bf[4];
#pragma unroll
        for (int mf = 0; mf < 4; mf++) {
            afl[mf] = *(const uint4*)&As[cur][wm0 + mf * 16 + gid][tig * 4];
            afh[mf] = *(const uint4*)&As[cur][wm0 + mf * 16 + 8 + gid][tig * 4];
        }
#pragma unroll
        for (int nf = 0; nf < 4; nf++)
            bf[nf] = *(const uint4*)&Bs[cur][wn0 + nf * 8 + gid][tig * 4];

#pragma unroll
        for (int mf = 0; mf < 4; mf++)
#pragma unroll
            for (int nf = 0; nf < 4; nf++) {
                MMA8(acc[mf][nf], afl[mf].x, afh[mf].x, afl[mf].y, afh[mf].y,
                     bf[nf].x, bf[nf].y);
                MMA8(acc[mf][nf], afl[mf].z, afh[mf].z, afl[mf].w, afh[mf].w,
                     bf[nf].z, bf[nf].w);
            }

        if (s + 1 < nst) {
            const int nxt = cur ^ 1;
#pragma unroll
            for (int e = 0; e < 8; e++) {
                int k = lkh + e;
                As[nxt][lr][((k & 3) << 2) | (k >> 2)] = f2tf(av[e]);
            }
            if (TRANSB) {
#pragma unroll
                for (int e = 0; e < 8; e++) {
                    int k = lkh + e;
                    Bs[nxt][lr][((k & 3) << 2) | (k >> 2)] = f2tf(bv[e]);
                }
            } else {
                int pc = ((vk & 3) << 2) | (vk >> 2);
#pragma unroll
                for (int e = 0; e < 8; e++) Bs[nxt][vn + e][pc] = f2tf(bv[e]);
            }
            __syncthreads();
        }
    }

    // ---- epilogue ----
#pragma unroll
    for (int mf = 0; mf < 4; mf++) {
        int mlo = m0 + wm0 + mf * 16 + gid;
        int mhi = mlo + 8;
#pragma unroll
        for (int nf = 0; nf < 4; nf++) {
            int nn = n0 + wn0 + nf * 8 + tig * 2;
            float b0 = HASBIAS ? bias[nn]     : 0.f;
            float b1 = HASBIAS ? bias[nn + 1] : 0.f;
            float v0 = acc[mf][nf].x + b0;
            float v1 = acc[mf][nf].y + b1;
            float v2 = acc[mf][nf].z + b0;
            float v3 = acc[mf][nf].w + b1;
            if (ACT == 1) {
                v0 = v0 >= 0.f ? v0 : 0.25f * v0;
                v1 = v1 >= 0.f ? v1 : 0.25f * v1;
                v2 = v2 >= 0.f ? v2 : 0.25f * v2;
                v3 = v3 >= 0.f ? v3 : 0.25f * v3;
            }
            *(float2*)&C[(long)mlo * ldc + nn] = make_float2(v0, v1);
            *(float2*)&C[(long)mhi * ldc + nn] = make_float2(v2, v3);
        }
    }
}

// ---------- 64x64 SGEMM kept only for the tiny final pooling GEMM ----------
template<int ACT, int TRANSB, int HASBIAS>
__global__ __launch_bounds__(256)
void gemm_kernel(const float* __restrict__ A, const float* __restrict__ Bm,
                 const float* __restrict__ bias, float* __restrict__ C,
                 int M, int N, int Kd, int lda, int ldb, int ldc,
                 int bInner, long sAo, long sAi, long sBo, long sBi,
                 long sCo, long sCi)
{
    int z  = blockIdx.z;
    int zo = z / bInner, zi = z % bInner;
    A  += zo * sAo + zi * sAi;
    Bm += zo * sBo + zi * sBi;
    C  += zo * sCo + zi * sCi;

    __shared__ float As[16][64];
    __shared__ float Bs[16][64];

    int tid = threadIdx.x;
    int tx = tid & 15, ty = tid >> 4;
    int m0 = blockIdx.y * 64, n0 = blockIdx.x * 64;
    int arow = tid >> 2, akq = (tid & 3) * 4;

    float acc[4][4];
#pragma unroll
    for (int i = 0; i < 4; i++)
#pragma unroll
        for (int j = 0; j < 4; j++) acc[i][j] = 0.f;

    for (int k0 = 0; k0 < Kd; k0 += 16) {
        {
            int m = m0 + arow;
            float4 v = make_float4(0.f, 0.f, 0.f, 0.f);
            if (m < M) v = *(const float4*)&A[(long)m * lda + k0 + akq];
            As[akq + 0][arow] = v.x; As[akq + 1][arow] = v.y;
            As[akq + 2][arow] = v.z; As[akq + 3][arow] = v.w;
        }
        if (TRANSB) {
            int nn = n0 + arow;
            float4 v = make_float4(0.f, 0.f, 0.f, 0.f);
            if (nn < N) v = *(const float4*)&Bm[(long)nn * ldb + k0 + akq];
            Bs[akq + 0][arow] = v.x; Bs[akq + 1][arow] = v.y;
            Bs[akq + 2][arow] = v.z; Bs[akq + 3][arow] = v.w;
        } else {
#pragma unroll
            for (int p = 0; p < 4; p++) {
                int kk = (tid >> 6) + p * 4;
                int nn = n0 + (tid & 63);
                float v = 0.f;
                if (nn < N) v = Bm[(long)(k0 + kk) * ldb + nn];
                Bs[kk][tid & 63] = v;
            }
        }
        __syncthreads();
#pragma unroll
        for (int kk = 0; kk < 16; kk++) {
            float4 av = *(const float4*)&As[kk][ty * 4];
            float4 bv = *(const float4*)&Bs[kk][tx * 4];
            float a[4] = {av.x, av.y, av.z, av.w};
            float b[4] = {bv.x, bv.y, bv.z, bv.w};
#pragma unroll
            for (int i = 0; i < 4; i++)
#pragma unroll
                for (int j = 0; j < 4; j++) acc[i][j] += a[i] * b[j];
        }
        __syncthreads();
    }
#pragma unroll
    for (int i = 0; i < 4; i++) {
        int m = m0 + ty * 4 + i;
        if (m >= M) continue;
#pragma unroll
        for (int j = 0; j < 4; j++) {
            int nn = n0 + tx * 4 + j;
            if (nn >= N) continue;
            float v = acc[i][j];
            if (HASBIAS) v += bias[nn];
            if (ACT == 1) v = v >= 0.f ? v : 0.25f * v;
            C[(long)m * ldc + nn] = v;
        }
    }
}

// ---------- softmax over rows of 1024 (in place), 256 threads ----------
__global__ void softmax_kernel(float* __restrict__ data)
{
    long row = blockIdx.x;
    float4* p = (float4*)(data + row * 1024);
    float4 v = p[threadIdx.x];
    int lane = threadIdx.x & 31, w = threadIdx.x >> 5;
    __shared__ float sm[8], ss[8];

    float m = fmaxf(fmaxf(v.x, v.y), fmaxf(v.z, v.w));
#pragma unroll
    for (int o = 16; o; o >>= 1) m = fmaxf(m, __shfl_xor_sync(0xffffffffu, m, o));
    if (lane == 0) sm[w] = m;
    __syncthreads();
    float bm = sm[0];
#pragma unroll
    for (int i = 1; i < 8; i++) bm = fmaxf(bm, sm[i]);

    v.x = __expf(v.x - bm); v.y = __expf(v.y - bm);
    v.z = __expf(v.z - bm); v.w = __expf(v.w - bm);
    float s = v.x + v.y + v.z + v.w;
#pragma unroll
    for (int o = 16; o; o >>= 1) s += __shfl_xor_sync(0xffffffffu, s, o);
    if (lane == 0) ss[w] = s;
    __syncthreads();
    float bs = ss[0] + ss[1] + ss[2] + ss[3] + ss[4] + ss[5] + ss[6] + ss[7];
    float inv = 1.f / bs;
    v.x *= inv; v.y *= inv; v.z *= inv; v.w *= inv;
    p[threadIdx.x] = v;
}

// ---------- LayerNorm over E=512, 128 threads ----------
__global__ void layernorm_kernel(const float* __restrict__ x, const float* __restrict__ g,
                                 const float* __restrict__ bta, float* __restrict__ y)
{
    long row = blockIdx.x;
    const float4* xr = (const float4*)(x + row * 512);
    float4 v = xr[threadIdx.x];
    int lane = threadIdx.x & 31, w = threadIdx.x >> 5;
    float s1 = v.x + v.y + v.z + v.w;
    float s2 = v.x * v.x + v.y * v.y + v.z * v.z + v.w * v.w;
#pragma unroll
    for (int o = 16; o; o >>= 1) {
        s1 += __shfl_xor_sync(0xffffffffu, s1, o);
        s2 += __shfl_xor_sync(0xffffffffu, s2, o);
    }
    __shared__ float a1s[4], a2s[4];
    if (lane == 0) { a1s[w] = s1; a2s[w] = s2; }
    __syncthreads();
    s1 = a1s[0] + a1s[1] + a1s[2] + a1s[3];
    s2 = a2s[0] + a2s[1] + a2s[2] + a2s[3];
    float mean = s1 * (1.f / 512.f);
    float var  = s2 * (1.f / 512.f) - mean * mean;
    float inv  = rsqrtf(var + 1e-5f);
    float4 gv = ((const float4*)g)[threadIdx.x];
    float4 bv = ((const float4*)bta)[threadIdx.x];
    float4 o4;
    o4.x = (v.x - mean) * inv * gv.x + bv.x;
    o4.y = (v.y - mean) * inv * gv.y + bv.y;
    o4.z = (v.z - mean) * inv * gv.z + bv.z;
    o4.w = (v.w - mean) * inv * gv.w + bv.w;
    ((float4*)(y + row * 512))[threadIdx.x] = o4;
}

__global__ void reset_kernel()
{
    int i = blockIdx.x * blockDim.x + threadIdx.x;
    if (i < 2 * B_ * H_) g_hbuf[i] = 0.f;
    if (i == 0) g_bar = 0u;
}

__device__ __forceinline__ float fsigmoid(float x) { return 1.f / (1.f + __expf(-x)); }
__device__ __forceinline__ float ftanh(float x)
{
    float e = __expf(2.f * x);
    return 1.f - 2.f / (e + 1.f);
}

#define LSTM_NB 128
__global__ __launch_bounds__(256, 1)
void lstm_kernel(const float* __restrict__ gx, const float* __restrict__ Whh,
                 const float* __restrict__ bhh, float* __restrict__ hbuf,
                 float* __restrict__ lstm_out)
{
    const int tid  = threadIdx.x;
    const int lane = tid & 31;
    const int w    = tid >> 5;
    const int bi   = blockIdx.x;

    __shared__ float sh[8][1024];
    __shared__ float sg[32][8];
    __shared__ float scs[8][8];

    float2 wreg[4][16];
#pragma unroll
    for (int r = 0; r < 4; r++) {
        int lr = w * 4 + r;
        int j  = (lr >> 3) * H_ + bi * 8 + (lr & 7);
        const float2* wrow = (const float2*)(Whh + (long)j * H_);
#pragma unroll
        for (int kk = 0; kk < 16; kk++) wreg[r][kk] = wrow[kk * 32 + lane];
    }

    const int oidx = ((lane & 1) << 3) | ((lane & 2) << 1) | ((lane & 4) >> 1) | ((lane & 8) >> 3);
    const int o_r = oidx >> 2, o_b = oidx & 3;

    int ul = tid >> 3, bb = tid & 7;
    int u  = bi * 8 + ul;
    float rb0 = 0.f, rb1 = 0.f, rb2 = 0.f, rb3 = 0.f;
    if (tid < 64) {
        rb0 = bhh[0 * H_ + u]; rb1 = bhh[1 * H_ + u];
        rb2 = bhh[2 * H_ + u]; rb3 = bhh[3 * H_ + u];
        scs[ul][bb] = 0.f;
    }

    unsigned target = 0;
    for (int t = 0; t < T_; t++) {
        float px0, px1, px2, px3;
        if (tid < 64) {
            long grow = ((long)bb * T_ + t) * G4_;
            px0 = gx[grow + 0 * H_ + u];
            px1 = gx[grow + 1 * H_ + u];
            px2 = gx[grow + 2 * H_ + u];
            px3 = gx[grow + 3 * H_ + u];
        }

        const float4* hr = (const float4*)(hbuf + (t & 1) * (B_ * H_));
        float*        hw =                 hbuf + ((t + 1) & 1) * (B_ * H_);
#pragma unroll
        for (int p = 0; p < 8; p++)
            ((float4*)&sh[0][0])[tid + p * 256] = hr[tid + p * 256];
        __syncthreads();

#pragma unroll
        for (int bh = 0; bh < 2; bh++) {
            float2 acc[4][4];
#pragma unroll
            for (int r = 0; r < 4; r++)
#pragma unroll
                for (int b = 0; b < 4; b++) acc[r][b] = make_float2(0.f, 0.f);
#pragma unroll
            for (int kk = 0; kk < 16; kk++) {
                float2 h2[4];
#pragma unroll
                for (int b = 0; b < 4; b++)
                    h2[b] = *(const float2*)&sh[bh * 4 + b][kk * 64 + lane * 2];
#pragma unroll
                for (int r = 0; r < 4; r++) {
                    float2 wv = wreg[r][kk];
#pragma unroll
                    for (int b = 0; b < 4; b++) acc[r][b] = ffma2(wv, h2[b], acc[r][b]);
                }
            }
            float vals[16];
#pragma unroll
            for (int r = 0; r < 4; r++)
#pragma unroll
                for (int b = 0; b < 4; b++) vals[r * 4 + b] = acc[r][b].x + acc[r][b].y;
            int cnt = 16;
#pragma unroll
            for (int d = 1; d <= 8; d <<= 1) {
                int half = cnt >> 1;
                bool up = (lane & d) != 0;
#pragma unroll
                for (int i = 0; i < 8; i++) {
                    if (i >= half) break;
                    float send = up ? vals[i] : vals[i + half];
                    float keep = up ? vals[i + half] : vals[i];
                    float recv = __shfl_xor_sync(0xffffffffu, send, d);
                    vals[i] = keep + recv;
                }
                cnt = half;
            }
            vals[0] += __shfl_xor_sync(0xffffffffu, vals[0], 16);
            if (lane < 16) sg[w * 4 + o_r][bh * 4 + o_b] = vals[0];
        }
        __syncthreads();

        if (tid < 64) {
            float gi = sg[0 * 8 + ul][bb] + px0 + rb0;
            float gf = sg[1 * 8 + ul][bb] + px1 + rb1;
            float gg = sg[2 * 8 + ul][bb] + px2 + rb2;
            float go = sg[3 * 8 + ul][bb] + px3 + rb3;
            float c  = fsigmoid(gf) * scs[ul][bb] + fsigmoid(gi) * ftanh(gg);
            float hn = fsigmoid(go) * ftanh(c);
            scs[ul][bb] = c;
            hw[bb * H_ + u] = hn;
            lstm_out[((long)bb * T_ + t) * H_ + u] = hn;
        }
        __syncthreads();

        target += LSTM_NB;
        if (tid == 0) {
            asm volatile("fence.acq_rel.gpu;" ::: "memory");
            atomicAdd(&g_bar, 1u);
            unsigned r;
            do {
                asm volatile("ld.global.acquire.gpu.u32 %0, [%1];"
                             : "=r"(r) : "l"(&g_bar));
            } while (r < target);
        }
        __syncthreads();
    }
}

// ---------- conv weight repack: w[c][h][dk] -> wt[dk][c][h] ----------
__global__ void repack_wc1(const float* __restrict__ w, float* __restrict__ wt)
{
    int idx = blockIdx.x * blockDim.x + threadIdx.x;
    if (idx < C1_ * H_ * 3) {
        int dk = idx % 3;
        int h  = (idx / 3) % H_;
        int c  = idx / (3 * H_);
        wt[(long)dk * C1_ * H_ + (long)c * H_ + h] = w[idx];
    }
}

// ---------- conv1 via 128x128 f32x2 tiles (split-column): relu(conv) -> [B,C1,T] ----------
__global__ __launch_bounds__(256)
void conv1_kernel(const float* __restrict__ X, const float* __restrict__ Wt,
                  const float* __restrict__ bias, float* __restrict__ Y)
{
    const int b  = blockIdx.z;
    const int t0 = blockIdx.y * 128, c0 = blockIdx.x * 128;
    __shared__ float As[16][128];
    __shared__ float Bs[16][128];
    const int tid = threadIdx.x;
    const int tx = tid & 15, ty = tid >> 4;
    const int lm = tid >> 1;
    const int lk = (tid & 1) * 8;

    float2 acc[4][8];
#pragma unroll
    for (int p = 0; p < 4; p++)
#pragma unroll
        for (int j = 0; j < 8; j++) acc[p][j] = make_float2(0.f, 0.f);

    for (int dk = 0; dk < 3; dk++) {
        const float* Wd = Wt + (long)dk * C1_ * H_;
        for (int k0 = 0; k0 < H_; k0 += 16) {
            {
                int t = t0 + lm + dk - 1;
                float4 a0 = make_float4(0.f, 0.f, 0.f, 0.f), a1 = a0;
                if (t >= 0 && t < T_) {
                    const float* ap = &X[((long)b * T_ + t) * H_ + k0 + lk];
                    a0 = *(const float4*)ap;
                    a1 = *(const float4*)(ap + 4);
                }
                As[lk + 0][lm] = a0.x; As[lk + 1][lm] = a0.y;
                As[lk + 2][lm] = a0.z; As[lk + 3][lm] = a0.w;
                As[lk + 4][lm] = a1.x; As[lk + 5][lm] = a1.y;
                As[lk + 6][lm] = a1.z; As[lk + 7][lm] = a1.w;
            }
            {
                const float* bp = &Wd[(long)(c0 + lm) * H_ + k0 + lk];
                float4 b0 = *(const float4*)bp;
                float4 b1 = *(const float4*)(bp + 4);
                Bs[lk + 0][lm] = b0.x; Bs[lk + 1][lm] = b0.y;
                Bs[lk + 2][lm] = b0.z; Bs[lk + 3][lm] = b0.w;
                Bs[lk + 4][lm] = b1.x; Bs[lk + 5][lm] = b1.y;
                Bs[lk + 6][lm] = b1.z; Bs[lk + 7][lm] = b1.w;
            }
            __syncthreads();
#pragma unroll
            for (int kk = 0; kk < 16; kk++) {
                float4 av0 = *(const float4*)&As[kk][ty * 8];
                float4 av1 = *(const float4*)&As[kk][ty * 8 + 4];
                float2 a2[4] = { make_float2(av0.x, av0.y), make_float2(av0.z, av0.w),
                                 make_float2(av1.x, av1.y), make_float2(av1.z, av1.w) };
                float4 bv0 = *(const float4*)&Bs[kk][tx * 4];
                float4 bv1 = *(const float4*)&Bs[kk][64 + tx * 4];
                float bj[8] = { bv0.x, bv0.y, bv0.z, bv0.w, bv1.x, bv1.y, bv1.z, bv1.w };
#pragma unroll
                for (int j = 0; j < 8; j++) {
                    float2 b2 = make_float2(bj[j], bj[j]);
#pragma unroll
                    for (int p = 0; p < 4; p++) acc[p][j] = ffma2(a2[p], b2, acc[p][j]);
                }
            }
            __syncthreads();
        }
    }
#pragma unroll
    for (int j = 0; j < 8; j++) {
        int c = c0 + (j < 4 ? tx * 4 + j : 64 + tx * 4 + (j - 4));
        float bvv = bias[c];
        float* yrow = &Y[((long)b * C1_ + c) * T_];
#pragma unroll
        for (int p = 0; p < 4; p++) {
            int t = t0 + ty * 8 + 2 * p;
            float v0 = acc[p][j].x + bvv;
            float v1 = acc[p][j].y + bvv;
            yrow[t]     = v0 > 0.f ? v0 : 0.f;
            yrow[t + 1] = v1 > 0.f ? v1 : 0.f;
        }
    }
}

// ---------- conv2: [B,C1,T] -> [B,2,T] ----------
__global__ void conv2_kernel(const float* __restrict__ A1, const float* __restrict__ W2,
                             const float* __restrict__ b2, float* __restrict__ A2)
{
    int b = blockIdx.y;
    int t = blockIdx.x * blockDim.x + threadIdx.x;
    float acc0 = b2[0], acc1 = b2[1];
    const float* base = A1 + (long)b * C1_ * T_;
    for (int c = 0; c < C1_; c++) {
        const float* row = base + (long)c * T_;
        float xm = (t >= 1)      ? row[t - 1] : 0.f;
        float x0 = row[t];
        float xp = (t <= T_ - 2) ? row[t + 1] : 0.f;
        const float* w0 = W2 + c * 3;
        const float* w1 = W2 + (C1_ + c) * 3;
        acc0 += xm * w0[0] + x0 * w0[1] + xp * w0[2];
        acc1 += xm * w1[0] + x0 * w1[1] + xp * w1[2];
    }
    A2[((long)b * 2 + 0) * T_ + t] = acc0;
    A2[((long)b * 2 + 1) * T_ + t] = acc1;
}

static float* sym(const void* s)
{
    void* p = nullptr;
    cudaGetSymbolAddress(&p, (const void*)s);
    return (float*)p;
}

extern "C" void kernel_launch(void* const* d_in, const int* in_sizes, int n_in,
                              void* d_out, int out_size)
{
    const float* x     = (const float*)d_in[0];
    const float* w_in1 = (const float*)d_in[1];
    const float* b_in1 = (const float*)d_in[2];
    const float* w_in2 = (const float*)d_in[3];
    const float* b_in2 = (const float*)d_in[4];
    const float* w_q   = (const float*)d_in[5];
    const float* b_q   = (const float*)d_in[6];
    const float* w_k   = (const float*)d_in[7];
    const float* b_k   = (const float*)d_in[8];
    const float* w_v   = (const float*)d_in[9];
    const float* b_v   = (const float*)d_in[10];
    const float* w_p   = (const float*)d_in[11];
    const float* b_p   = (const float*)d_in[12];
    const float* ln_g  = (const float*)d_in[13];
    const float* ln_b  = (const float*)d_in[14];
    const float* w_ih  = (const float*)d_in[15];
    const float* w_hh  = (const float*)d_in[16];
    const float* b_ih  = (const float*)d_in[17];
    const float* b_hh  = (const float*)d_in[18];
    const float* w_c1  = (const float*)d_in[19];
    const float* b_c1  = (const float*)d_in[20];
    const float* w_c2  = (const float*)d_in[21];
    const float* b_c2  = (const float*)d_in[22];
    float* out = (float*)d_out;

    float* h1   = sym(g_h1);
    float* hh   = sym(g_hh);
    float* q    = sym(g_q);
    float* k    = sym(g_k);
    float* v    = sym(g_v);
    float* sc   = sym(g_sc);
    float* o    = sym(g_o);
    float* y    = sym(g_y);
    float* gx   = sym(g_gx);
    float* lstm = sym(g_lstm);
    float* hbuf = sym(g_hbuf);
    float* a1   = sym(g_a1);
    float* a2   = sym(g_a2);
    float* wc1t = sym(g_wc1t);

    dim3 blk(256);

    // in_pro: 1x1 -> leaky -> 1x1
    gemm_tf32<1,1,1><<<dim3(4,64,1), blk>>>(x, w_in1, b_in1, h1,
        BT_, E_, E_, E_, E_, E_, 1, 0,0,0,0,0,0);
    gemm_tf32<0,1,1><<<dim3(4,64,1), blk>>>(h1, w_in2, b_in2, hh,
        BT_, E_, E_, E_, E_, E_, 1, 0,0,0,0,0,0);

    // QKV
    gemm_tf32<0,1,1><<<dim3(8,64,1), blk>>>(hh, w_q, b_q, q,
        BT_, NH_*QD_, E_, E_, E_, NH_*QD_, 1, 0,0,0,0,0,0);
    gemm_tf32<0,1,1><<<dim3(8,64,1), blk>>>(hh, w_k, b_k, k,
        BT_, NH_*QD_, E_, E_, E_, NH_*QD_, 1, 0,0,0,0,0,0);
    gemm_tf32<0,1,1><<<dim3(16,64,1), blk>>>(hh, w_v, b_v, v,
        BT_, NH_*VD_, E_, E_, E_, NH_*VD_, 1, 0,0,0,0,0,0);

    // scores = q @ k^T per (b, head)
    gemm_tf32<0,1,0><<<dim3(8,8,B_*NH_), blk>>>(q, k, nullptr, sc,
        T_, T_, QD_, NH_*QD_, NH_*QD_, T_, NH_,
        (long)T_*NH_*QD_, (long)QD_, (long)T_*NH_*QD_, (long)QD_,
        (long)NH_*T_*T_, (long)T_*T_);

    softmax_kernel<<<B_*NH_*T_, 256>>>(sc);

    // o = attn @ v per (b, head)
    gemm_tf32<0,0,0><<<dim3(4,8,B_*NH_), blk>>>(sc, v, nullptr, o,
        T_, VD_, T_, T_, NH_*VD_, NH_*VD_, NH_,
        (long)NH_*T_*T_, (long)T_*T_, (long)T_*NH_*VD_, (long)VD_,
        (long)T_*NH_*VD_, (long)VD_);

    // out projection + layernorm
    gemm_tf32<0,1,1><<<dim3(4,64,1), blk>>>(o, w_p, b_p, y,
        BT_, E_, NH_*VD_, NH_*VD_, NH_*VD_, E_, 1, 0,0,0,0,0,0);
    layernorm_kernel<<<BT_, 128>>>(y, ln_g, ln_b, y);

    // LSTM input GEMM: gx = y @ w_ih^T + b_ih
    gemm_tf32<0,1,1><<<dim3(32,64,1), blk>>>(y, w_ih, b_ih, gx,
        BT_, G4_, E_, E_, E_, G4_, 1, 0,0,0,0,0,0);

    reset_kernel<<<64, 256>>>();
    lstm_kernel<<<LSTM_NB, 256>>>(gx, w_hh, b_hh, hbuf, lstm);

    // conv pooling
    repack_wc1<<<(C1_*H_*3 + 255)/256, 256>>>(w_c1, wc1t);
    conv1_kernel<<<dim3(4,8,B_), blk>>>(lstm, wc1t, b_c1, a1);
    conv2_kernel<<<dim3(4,B_), 256>>>(a1, w_c2, b_c2, a2);
    softmax_kernel<<<B_*C2_, 256>>>(a2);

    // feat = a2 @ lstm_out : [2,1024]@[1024,1024] per batch -> out [8,2048]
    gemm_kernel<0,0,0><<<dim3(16,1,B_), blk>>>(a2, lstm, nullptr, out,
        C2_, H_, T_, T_, H_, H_, 1,
        (long)C2_*T_, 0, (long)T_*H_, 0, (long)C2_*H_, 0);
}

// round 13
// speedup vs baseline: 1.7026x; 1.0430x over previous
#include <cuda_runtime.h>

#define B_   8
#define T_   1024
#define E_   512
#define H_   1024
#define NH_  4
#define QD_  256
#define VD_  512
#define C1_  512
#define C2_  2
#define BT_  (B_ * T_)
#define G4_  (4 * H_)

__device__ float g_h1[(size_t)BT_ * E_];
__device__ float g_hh[(size_t)BT_ * E_];
__device__ float g_q [(size_t)BT_ * (NH_ * QD_)];
__device__ float g_k [(size_t)BT_ * (NH_ * QD_)];
__device__ float g_v [(size_t)BT_ * (NH_ * VD_)];
__device__ float g_sc[(size_t)B_ * NH_ * T_ * T_];
__device__ float g_o [(size_t)BT_ * (NH_ * VD_)];
__device__ float g_y [(size_t)BT_ * E_];
__device__ float g_gx[(size_t)BT_ * G4_];
__device__ float g_lstm[(size_t)BT_ * H_];
__device__ float g_hbuf[2 * B_ * H_];
__device__ float g_a1[(size_t)B_ * C1_ * T_];
__device__ float g_a2[(size_t)B_ * C2_ * T_];
__device__ float g_wc1t[(size_t)3 * C1_ * H_];
__device__ unsigned g_bar;

__device__ __forceinline__ float2 ffma2(float2 a, float2 b, float2 c)
{
    unsigned long long A = *reinterpret_cast<unsigned long long*>(&a);
    unsigned long long Bb = *reinterpret_cast<unsigned long long*>(&b);
    unsigned long long Cc = *reinterpret_cast<unsigned long long*>(&c);
    unsigned long long D;
    asm("fma.rn.f32x2 %0, %1, %2, %3;" : "=l"(D) : "l"(A), "l"(Bb), "l"(Cc));
    return *reinterpret_cast<float2*>(&D);
}

__device__ __forceinline__ unsigned f2tf(float x)
{
    unsigned r;
    asm("cvt.rna.tf32.f32 %0, %1;" : "=r"(r) : "f"(x));
    return r;
}

#define MMA8(d, A0, A1, A2, A3, B0, B1) \
    asm("mma.sync.aligned.m16n8k8.row.col.f32.tf32.tf32.f32 " \
        "{%0,%1,%2,%3},{%4,%5,%6,%7},{%8,%9},{%0,%1,%2,%3};" \
        : "+f"(d.x), "+f"(d.y), "+f"(d.z), "+f"(d.w) \
        : "r"(A0), "r"(A1), "r"(A2), "r"(A3), "r"(B0), "r"(B1))

// ========== 128x128 TF32 GEMM, 4 warps x (64x64), swizzled smem ==========
// C = act(A @ op(B) + bias). A:[M,K] row-major. TRANSB=1: B:[N,K]; 0: B:[K,N].
// Requires: M%128==0, N%128==0, K%16==0.
// Smem rows hold 16 tf32 in k-permuted order (word c holds k = (c>>2) + 4*(c&3),
// a self-inverse permutation), with XOR group swizzle g' = g ^ ((row>>1)&3) so
// that both STS.128 stores and LDS.128 fragment loads are bank-conflict-free.
template<int ACT, int TRANSB, int HASBIAS>
__global__ __launch_bounds__(128)
void gemm_tf32(const float* __restrict__ A, const float* __restrict__ Bm,
               const float* __restrict__ bias, float* __restrict__ C,
               int M, int N, int Kd, int lda, int ldb, int ldc,
               int bInner, long sAo, long sAi, long sBo, long sBi,
               long sCo, long sCi)
{
    int z  = blockIdx.z;
    int zo = z / bInner, zi = z % bInner;
    A  += zo * sAo + zi * sAi;
    Bm += zo * sBo + zi * sBi;
    C  += zo * sCo + zi * sCi;

    __shared__ __align__(16) unsigned As[2][128][16];
    __shared__ __align__(16) unsigned Bs[2][128][16];

    const int tid  = threadIdx.x;
    const int lane = tid & 31, wid = tid >> 5;
    const int gid  = lane >> 2, tig = lane & 3;
    const int wm0  = (wid & 1) * 64, wn0 = (wid >> 1) * 64;
    const int m0   = blockIdx.y * 128, n0 = blockIdx.x * 128;

    const int lr  = tid;                      // A (and B when TRANSB=1) row
    const int tk  = tid & 15;                 // TRANSB=0: k within slab
    const int tn0 = (tid >> 4) * 16;          // TRANSB=0: n start

    float4 acc[4][8];
#pragma unroll
    for (int mf = 0; mf < 4; mf++)
#pragma unroll
        for (int nf = 0; nf < 8; nf++) acc[mf][nf] = make_float4(0.f, 0.f, 0.f, 0.f);

    float av[16], bv[16];

#define LOAD_SLAB(k0) do { \
        const float* p_ = &A[(long)(m0 + lr) * lda + (k0)]; \
        float4 v0_ = *(const float4*)p_, v1_ = *(const float4*)(p_ + 4); \
        float4 v2_ = *(const float4*)(p_ + 8), v3_ = *(const float4*)(p_ + 12); \
        av[0]=v0_.x; av[1]=v0_.y; av[2]=v0_.z; av[3]=v0_.w; \
        av[4]=v1_.x; av[5]=v1_.y; av[6]=v1_.z; av[7]=v1_.w; \
        av[8]=v2_.x; av[9]=v2_.y; av[10]=v2_.z; av[11]=v2_.w; \
        av[12]=v3_.x; av[13]=v3_.y; av[14]=v3_.z; av[15]=v3_.w; \
        const float* q_ = TRANSB ? &Bm[(long)(n0 + lr) * ldb + (k0)] \
                                 : &Bm[(long)((k0) + tk) * ldb + n0 + tn0]; \
        float4 w0_ = *(const float4*)q_, w1_ = *(const float4*)(q_ + 4); \
        float4 w2_ = *(const float4*)(q_ + 8), w3_ = *(const float4*)(q_ + 12); \
        bv[0]=w0_.x; bv[1]=w0_.y; bv[2]=w0_.z; bv[3]=w0_.w; \
        bv[4]=w1_.x; bv[5]=w1_.y; bv[6]=w1_.z; bv[7]=w1_.w; \
        bv[8]=w2_.x; bv[9]=w2_.y; bv[10]=w2_.z; bv[11]=w2_.w; \
        bv[12]=w3_.x; bv[13]=w3_.y; bv[14]=w3_.z; bv[15]=w3_.w; \
    } while (0)

#define STORE_SLAB(bf) do { \
        int asw_ = (lr >> 1) & 3; \
        _Pragma("unroll") \
        for (int g_ = 0; g_ < 4; g_++) { \
            uint4 u_ = make_uint4(f2tf(av[g_]), f2tf(av[g_ + 4]), \
                                  f2tf(av[g_ + 8]), f2tf(av[g_ + 12])); \
            *(uint4*)&As[bf][lr][(g_ ^ asw_) << 2] = u_; \
        } \
        if (TRANSB) { \
            _Pragma("unroll") \
            for (int g_ = 0; g_ < 4; g_++) { \
                uint4 u_ = make_uint4(f2tf(bv[g_]), f2tf(bv[g_ + 4]), \
                                      f2tf(bv[g_ + 8]), f2tf(bv[g_ + 12])); \
                *(uint4*)&Bs[bf][lr][(g_ ^ asw_) << 2] = u_; \
            } \
        } else { \
            int gk_ = tk & 3, ok_ = tk >> 2; \
            _Pragma("unroll") \
            for (int e_ = 0; e_ < 16; e_++) { \
                int n_ = tn0 + e_; \
                Bs[bf][n_][((gk_ ^ ((n_ >> 1) & 3)) << 2) | ok_] = f2tf(bv[e_]); \
            } \
        } \
    } while (0)

    LOAD_SLAB(0);
    STORE_SLAB(0);
    __syncthreads();

    const int nst = Kd >> 4;
    for (int s = 0; s < nst; s++) {
        const int cur = s & 1;
        if (s + 1 < nst) LOAD_SLAB((s + 1) << 4);

        uint4 afl[4], afh[4], bf[8];
#pragma unroll
        for (int mf = 0; mf < 4; mf++) {
            int r0 = wm0 + mf * 16 + gid;
            int sw = (tig ^ ((r0 >> 1) & 3)) << 2;
            afl[mf] = *(const uint4*)&As[cur][r0][sw];
            afh[mf] = *(const uint4*)&As[cur][r0 + 8][sw];
        }
#pragma unroll
        for (int nf = 0; nf < 8; nf++) {
            int r = wn0 + nf * 8 + gid;
            bf[nf] = *(const uint4*)&Bs[cur][r][(tig ^ ((r >> 1) & 3)) << 2];
        }

#pragma unroll
        for (int mf = 0; mf < 4; mf++)
#pragma unroll
            for (int nf = 0; nf < 8; nf++) {
                MMA8(acc[mf][nf], afl[mf].x, afh[mf].x, afl[mf].y, afh[mf].y,
                     bf[nf].x, bf[nf].y);
                MMA8(acc[mf][nf], afl[mf].z, afh[mf].z, afl[mf].w, afh[mf].w,
                     bf[nf].z, bf[nf].w);
            }

        if (s + 1 < nst) {
            STORE_SLAB(cur ^ 1);
            __syncthreads();
        }
    }
#undef LOAD_SLAB
#undef STORE_SLAB

    // ---- epilogue ----
#pragma unroll
    for (int mf = 0; mf < 4; mf++) {
        int mlo = m0 + wm0 + mf * 16 + gid;
        int mhi = mlo + 8;
#pragma unroll
        for (int nf = 0; nf < 8; nf++) {
            int nn = n0 + wn0 + nf * 8 + tig * 2;
            float b0 = HASBIAS ? bias[nn]     : 0.f;
            float b1 = HASBIAS ? bias[nn + 1] : 0.f;
            float v0 = acc[mf][nf].x + b0;
            float v1 = acc[mf][nf].y + b1;
            float v2 = acc[mf][nf].z + b0;
            float v3 = acc[mf][nf].w + b1;
            if (ACT == 1) {
                v0 = v0 >= 0.f ? v0 : 0.25f * v0;
                v1 = v1 >= 0.f ? v1 : 0.25f * v1;
                v2 = v2 >= 0.f ? v2 : 0.25f * v2;
                v3 = v3 >= 0.f ? v3 : 0.25f * v3;
            }
            *(float2*)&C[(long)mlo * ldc + nn] = make_float2(v0, v1);
            *(float2*)&C[(long)mhi * ldc + nn] = make_float2(v2, v3);
        }
    }
}

// ---------- 64x64 SGEMM kept only for the tiny final pooling GEMM ----------
template<int ACT, int TRANSB, int HASBIAS>
__global__ __launch_bounds__(256)
void gemm_kernel(const float* __restrict__ A, const float* __restrict__ Bm,
                 const float* __restrict__ bias, float* __restrict__ C,
                 int M, int N, int Kd, int lda, int ldb, int ldc,
                 int bInner, long sAo, long sAi, long sBo, long sBi,
                 long sCo, long sCi)
{
    int z  = blockIdx.z;
    int zo = z / bInner, zi = z % bInner;
    A  += zo * sAo + zi * sAi;
    Bm += zo * sBo + zi * sBi;
    C  += zo * sCo + zi * sCi;

    __shared__ float As[16][64];
    __shared__ float Bs[16][64];

    int tid = threadIdx.x;
    int tx = tid & 15, ty = tid >> 4;
    int m0 = blockIdx.y * 64, n0 = blockIdx.x * 64;
    int arow = tid >> 2, akq = (tid & 3) * 4;

    float acc[4][4];
#pragma unroll
    for (int i = 0; i < 4; i++)
#pragma unroll
        for (int j = 0; j < 4; j++) acc[i][j] = 0.f;

    for (int k0 = 0; k0 < Kd; k0 += 16) {
        {
            int m = m0 + arow;
            float4 v = make_float4(0.f, 0.f, 0.f, 0.f);
            if (m < M) v = *(const float4*)&A[(long)m * lda + k0 + akq];
            As[akq + 0][arow] = v.x; As[akq + 1][arow] = v.y;
            As[akq + 2][arow] = v.z; As[akq + 3][arow] = v.w;
        }
        if (TRANSB) {
            int nn = n0 + arow;
            float4 v = make_float4(0.f, 0.f, 0.f, 0.f);
            if (nn < N) v = *(const float4*)&Bm[(long)nn * ldb + k0 + akq];
            Bs[akq + 0][arow] = v.x; Bs[akq + 1][arow] = v.y;
            Bs[akq + 2][arow] = v.z; Bs[akq + 3][arow] = v.w;
        } else {
#pragma unroll
            for (int p = 0; p < 4; p++) {
                int kk = (tid >> 6) + p * 4;
                int nn = n0 + (tid & 63);
                float v = 0.f;
                if (nn < N) v = Bm[(long)(k0 + kk) * ldb + nn];
                Bs[kk][tid & 63] = v;
            }
        }
        __syncthreads();
#pragma unroll
        for (int kk = 0; kk < 16; kk++) {
            float4 av = *(const float4*)&As[kk][ty * 4];
            float4 bv = *(const float4*)&Bs[kk][tx * 4];
            float a[4] = {av.x, av.y, av.z, av.w};
            float b[4] = {bv.x, bv.y, bv.z, bv.w};
#pragma unroll
            for (int i = 0; i < 4; i++)
#pragma unroll
                for (int j = 0; j < 4; j++) acc[i][j] += a[i] * b[j];
        }
        __syncthreads();
    }
#pragma unroll
    for (int i = 0; i < 4; i++) {
        int m = m0 + ty * 4 + i;
        if (m >= M) continue;
#pragma unroll
        for (int j = 0; j < 4; j++) {
            int nn = n0 + tx * 4 + j;
            if (nn >= N) continue;
            float v = acc[i][j];
            if (HASBIAS) v += bias[nn];
            if (ACT == 1) v = v >= 0.f ? v : 0.25f * v;
            C[(long)m * ldc + nn] = v;
        }
    }
}

// ---------- softmax over rows of 1024 (in place), 256 threads ----------
__global__ void softmax_kernel(float* __restrict__ data)
{
    long row = blockIdx.x;
    float4* p = (float4*)(data + row * 1024);
    float4 v = p[threadIdx.x];
    int lane = threadIdx.x & 31, w = threadIdx.x >> 5;
    __shared__ float sm[8], ss[8];

    float m = fmaxf(fmaxf(v.x, v.y), fmaxf(v.z, v.w));
#pragma unroll
    for (int o = 16; o; o >>= 1) m = fmaxf(m, __shfl_xor_sync(0xffffffffu, m, o));
    if (lane == 0) sm[w] = m;
    __syncthreads();
    float bm = sm[0];
#pragma unroll
    for (int i = 1; i < 8; i++) bm = fmaxf(bm, sm[i]);

    v.x = __expf(v.x - bm); v.y = __expf(v.y - bm);
    v.z = __expf(v.z - bm); v.w = __expf(v.w - bm);
    float s = v.x + v.y + v.z + v.w;
#pragma unroll
    for (int o = 16; o; o >>= 1) s += __shfl_xor_sync(0xffffffffu, s, o);
    if (lane == 0) ss[w] = s;
    __syncthreads();
    float bs = ss[0] + ss[1] + ss[2] + ss[3] + ss[4] + ss[5] + ss[6] + ss[7];
    float inv = 1.f / bs;
    v.x *= inv; v.y *= inv; v.z *= inv; v.w *= inv;
    p[threadIdx.x] = v;
}

// ---------- LayerNorm over E=512, 128 threads ----------
__global__ void layernorm_kernel(const float* __restrict__ x, const float* __restrict__ g,
                                 const float* __restrict__ bta, float* __restrict__ y)
{
    long row = blockIdx.x;
    const float4* xr = (const float4*)(x + row * 512);
    float4 v = xr[threadIdx.x];
    int lane = threadIdx.x & 31, w = threadIdx.x >> 5;
    float s1 = v.x + v.y + v.z + v.w;
    float s2 = v.x * v.x + v.y * v.y + v.z * v.z + v.w * v.w;
#pragma unroll
    for (int o = 16; o; o >>= 1) {
        s1 += __shfl_xor_sync(0xffffffffu, s1, o);
        s2 += __shfl_xor_sync(0xffffffffu, s2, o);
    }
    __shared__ float a1s[4], a2s[4];
    if (lane == 0) { a1s[w] = s1; a2s[w] = s2; }
    __syncthreads();
    s1 = a1s[0] + a1s[1] + a1s[2] + a1s[3];
    s2 = a2s[0] + a2s[1] + a2s[2] + a2s[3];
    float mean = s1 * (1.f / 512.f);
    float var  = s2 * (1.f / 512.f) - mean * mean;
    float inv  = rsqrtf(var + 1e-5f);
    float4 gv = ((const float4*)g)[threadIdx.x];
    float4 bv = ((const float4*)bta)[threadIdx.x];
    float4 o4;
    o4.x = (v.x - mean) * inv * gv.x + bv.x;
    o4.y = (v.y - mean) * inv * gv.y + bv.y;
    o4.z = (v.z - mean) * inv * gv.z + bv.z;
    o4.w = (v.w - mean) * inv * gv.w + bv.w;
    ((float4*)(y + row * 512))[threadIdx.x] = o4;
}

__global__ void reset_kernel()
{
    int i = blockIdx.x * blockDim.x + threadIdx.x;
    if (i < 2 * B_ * H_) g_hbuf[i] = 0.f;
    if (i == 0) g_bar = 0u;
}

__device__ __forceinline__ float fsigmoid(float x) { return 1.f / (1.f + __expf(-x)); }
__device__ __forceinline__ float ftanh(float x)
{
    float e = __expf(2.f * x);
    return 1.f - 2.f / (e + 1.f);
}

#define LSTM_NB 128
__global__ __launch_bounds__(256, 1)
void lstm_kernel(const float* __restrict__ gx, const float* __restrict__ Whh,
                 const float* __restrict__ bhh, float* __restrict__ hbuf,
                 float* __restrict__ lstm_out)
{
    const int tid  = threadIdx.x;
    const int lane = tid & 31;
    const int w    = tid >> 5;
    const int bi   = blockIdx.x;

    __shared__ float sh[8][1024];
    __shared__ float sg[32][8];
    __shared__ float scs[8][8];

    float2 wreg[4][16];
#pragma unroll
    for (int r = 0; r < 4; r++) {
        int lr = w * 4 + r;
        int j  = (lr >> 3) * H_ + bi * 8 + (lr & 7);
        const float2* wrow = (const float2*)(Whh + (long)j * H_);
#pragma unroll
        for (int kk = 0; kk < 16; kk++) wreg[r][kk] = wrow[kk * 32 + lane];
    }

    const int oidx = ((lane & 1) << 3) | ((lane & 2) << 1) | ((lane & 4) >> 1) | ((lane & 8) >> 3);
    const int o_r = oidx >> 2, o_b = oidx & 3;

    int ul = tid >> 3, bb = tid & 7;
    int u  = bi * 8 + ul;
    float rb0 = 0.f, rb1 = 0.f, rb2 = 0.f, rb3 = 0.f;
    if (tid < 64) {
        rb0 = bhh[0 * H_ + u]; rb1 = bhh[1 * H_ + u];
        rb2 = bhh[2 * H_ + u]; rb3 = bhh[3 * H_ + u];
        scs[ul][bb] = 0.f;
    }

    unsigned target = 0;
    for (int t = 0; t < T_; t++) {
        float px0, px1, px2, px3;
        if (tid < 64) {
            long grow = ((long)bb * T_ + t) * G4_;
            px0 = gx[grow + 0 * H_ + u];
            px1 = gx[grow + 1 * H_ + u];
            px2 = gx[grow + 2 * H_ + u];
            px3 = gx[grow + 3 * H_ + u];
        }

        const float4* hr = (const float4*)(hbuf + (t & 1) * (B_ * H_));
        float*        hw =                 hbuf + ((t + 1) & 1) * (B_ * H_);
#pragma unroll
        for (int p = 0; p < 8; p++)
            ((float4*)&sh[0][0])[tid + p * 256] = hr[tid + p * 256];
        __syncthreads();

#pragma unroll
        for (int bh = 0; bh < 2; bh++) {
            float2 acc[4][4];
#pragma unroll
            for (int r = 0; r < 4; r++)
#pragma unroll
                for (int b = 0; b < 4; b++) acc[r][b] = make_float2(0.f, 0.f);
#pragma unroll
            for (int kk = 0; kk < 16; kk++) {
                float2 h2[4];
#pragma unroll
                for (int b = 0; b < 4; b++)
                    h2[b] = *(const float2*)&sh[bh * 4 + b][kk * 64 + lane * 2];
#pragma unroll
                for (int r = 0; r < 4; r++) {
                    float2 wv = wreg[r][kk];
#pragma unroll
                    for (int b = 0; b < 4; b++) acc[r][b] = ffma2(wv, h2[b], acc[r][b]);
                }
            }
            float vals[16];
#pragma unroll
            for (int r = 0; r < 4; r++)
#pragma unroll
                for (int b = 0; b < 4; b++) vals[r * 4 + b] = acc[r][b].x + acc[r][b].y;
            int cnt = 16;
#pragma unroll
            for (int d = 1; d <= 8; d <<= 1) {
                int half = cnt >> 1;
                bool up = (lane & d) != 0;
#pragma unroll
                for (int i = 0; i < 8; i++) {
                    if (i >= half) break;
                    float send = up ? vals[i] : vals[i + half];
                    float keep = up ? vals[i + half] : vals[i];
                    float recv = __shfl_xor_sync(0xffffffffu, send, d);
                    vals[i] = keep + recv;
                }
                cnt = half;
            }
            vals[0] += __shfl_xor_sync(0xffffffffu, vals[0], 16);
            if (lane < 16) sg[w * 4 + o_r][bh * 4 + o_b] = vals[0];
        }
        __syncthreads();

        if (tid < 64) {
            float gi = sg[0 * 8 + ul][bb] + px0 + rb0;
            float gf = sg[1 * 8 + ul][bb] + px1 + rb1;
            float gg = sg[2 * 8 + ul][bb] + px2 + rb2;
            float go = sg[3 * 8 + ul][bb] + px3 + rb3;
            float c  = fsigmoid(gf) * scs[ul][bb] + fsigmoid(gi) * ftanh(gg);
            float hn = fsigmoid(go) * ftanh(c);
            scs[ul][bb] = c;
            hw[bb * H_ + u] = hn;
            lstm_out[((long)bb * T_ + t) * H_ + u] = hn;
        }
        __syncthreads();

        target += LSTM_NB;
        if (tid == 0) {
            asm volatile("fence.acq_rel.gpu;" ::: "memory");
            atomicAdd(&g_bar, 1u);
            unsigned r;
            do {
                asm volatile("ld.global.acquire.gpu.u32 %0, [%1];"
                             : "=r"(r) : "l"(&g_bar));
            } while (r < target);
        }
        __syncthreads();
    }
}

// ---------- conv weight repack: w[c][h][dk] -> wt[dk][c][h] ----------
__global__ void repack_wc1(const float* __restrict__ w, float* __restrict__ wt)
{
    int idx = blockIdx.x * blockDim.x + threadIdx.x;
    if (idx < C1_ * H_ * 3) {
        int dk = idx % 3;
        int h  = (idx / 3) % H_;
        int c  = idx / (3 * H_);
        wt[(long)dk * C1_ * H_ + (long)c * H_ + h] = w[idx];
    }
}

// ---------- conv1 via 128x128 f32x2 tiles (split-column): relu(conv) -> [B,C1,T] ----------
__global__ __launch_bounds__(256)
void conv1_kernel(const float* __restrict__ X, const float* __restrict__ Wt,
                  const float* __restrict__ bias, float* __restrict__ Y)
{
    const int b  = blockIdx.z;
    const int t0 = blockIdx.y * 128, c0 = blockIdx.x * 128;
    __shared__ float As[16][128];
    __shared__ float Bs[16][128];
    const int tid = threadIdx.x;
    const int tx = tid & 15, ty = tid >> 4;
    const int lm = tid >> 1;
    const int lk = (tid & 1) * 8;

    float2 acc[4][8];
#pragma unroll
    for (int p = 0; p < 4; p++)
#pragma unroll
        for (int j = 0; j < 8; j++) acc[p][j] = make_float2(0.f, 0.f);

    for (int dk = 0; dk < 3; dk++) {
        const float* Wd = Wt + (long)dk * C1_ * H_;
        for (int k0 = 0; k0 < H_; k0 += 16) {
            {
                int t = t0 + lm + dk - 1;
                float4 a0 = make_float4(0.f, 0.f, 0.f, 0.f), a1 = a0;
                if (t >= 0 && t < T_) {
                    const float* ap = &X[((long)b * T_ + t) * H_ + k0 + lk];
                    a0 = *(const float4*)ap;
                    a1 = *(const float4*)(ap + 4);
                }
                As[lk + 0][lm] = a0.x; As[lk + 1][lm] = a0.y;
                As[lk + 2][lm] = a0.z; As[lk + 3][lm] = a0.w;
                As[lk + 4][lm] = a1.x; As[lk + 5][lm] = a1.y;
                As[lk + 6][lm] = a1.z; As[lk + 7][lm] = a1.w;
            }
            {
                const float* bp = &Wd[(long)(c0 + lm) * H_ + k0 + lk];
                float4 b0 = *(const float4*)bp;
                float4 b1 = *(const float4*)(bp + 4);
                Bs[lk + 0][lm] = b0.x; Bs[lk + 1][lm] = b0.y;
                Bs[lk + 2][lm] = b0.z; Bs[lk + 3][lm] = b0.w;
                Bs[lk + 4][lm] = b1.x; Bs[lk + 5][lm] = b1.y;
                Bs[lk + 6][lm] = b1.z; Bs[lk + 7][lm] = b1.w;
            }
            __syncthreads();
#pragma unroll
            for (int kk = 0; kk < 16; kk++) {
                float4 av0 = *(const float4*)&As[kk][ty * 8];
                float4 av1 = *(const float4*)&As[kk][ty * 8 + 4];
                float2 a2[4] = { make_float2(av0.x, av0.y), make_float2(av0.z, av0.w),
                                 make_float2(av1.x, av1.y), make_float2(av1.z, av1.w) };
                float4 bv0 = *(const float4*)&Bs[kk][tx * 4];
                float4 bv1 = *(const float4*)&Bs[kk][64 + tx * 4];
                float bj[8] = { bv0.x, bv0.y, bv0.z, bv0.w, bv1.x, bv1.y, bv1.z, bv1.w };
#pragma unroll
                for (int j = 0; j < 8; j++) {
                    float2 b2 = make_float2(bj[j], bj[j]);
#pragma unroll
                    for (int p = 0; p < 4; p++) acc[p][j] = ffma2(a2[p], b2, acc[p][j]);
                }
            }
            __syncthreads();
        }
    }
#pragma unroll
    for (int j = 0; j < 8; j++) {
        int c = c0 + (j < 4 ? tx * 4 + j : 64 + tx * 4 + (j - 4));
        float bvv = bias[c];
        float* yrow = &Y[((long)b * C1_ + c) * T_];
#pragma unroll
        for (int p = 0; p < 4; p++) {
            int t = t0 + ty * 8 + 2 * p;
            float v0 = acc[p][j].x + bvv;
            float v1 = acc[p][j].y + bvv;
            yrow[t]     = v0 > 0.f ? v0 : 0.f;
            yrow[t + 1] = v1 > 0.f ? v1 : 0.f;
        }
    }
}

// ---------- conv2: [B,C1,T] -> [B,2,T] ----------
__global__ void conv2_kernel(const float* __restrict__ A1, const float* __restrict__ W2,
                             const float* __restrict__ b2, float* __restrict__ A2)
{
    int b = blockIdx.y;
    int t = blockIdx.x * blockDim.x + threadIdx.x;
    float acc0 = b2[0], acc1 = b2[1];
    const float* base = A1 + (long)b * C1_ * T_;
    for (int c = 0; c < C1_; c++) {
        const float* row = base + (long)c * T_;
        float xm = (t >= 1)      ? row[t - 1] : 0.f;
        float x0 = row[t];
        float xp = (t <= T_ - 2) ? row[t + 1] : 0.f;
        const float* w0 = W2 + c * 3;
        const float* w1 = W2 + (C1_ + c) * 3;
        acc0 += xm * w0[0] + x0 * w0[1] + xp * w0[2];
        acc1 += xm * w1[0] + x0 * w1[1] + xp * w1[2];
    }
    A2[((long)b * 2 + 0) * T_ + t] = acc0;
    A2[((long)b * 2 + 1) * T_ + t] = acc1;
}

static float* sym(const void* s)
{
    void* p = nullptr;
    cudaGetSymbolAddress(&p, (const void*)s);
    return (float*)p;
}

extern "C" void kernel_launch(void* const* d_in, const int* in_sizes, int n_in,
                              void* d_out, int out_size)
{
    const float* x     = (const float*)d_in[0];
    const float* w_in1 = (const float*)d_in[1];
    const float* b_in1 = (const float*)d_in[2];
    const float* w_in2 = (const float*)d_in[3];
    const float* b_in2 = (const float*)d_in[4];
    const float* w_q   = (const float*)d_in[5];
    const float* b_q   = (const float*)d_in[6];
    const float* w_k   = (const float*)d_in[7];
    const float* b_k   = (const float*)d_in[8];
    const float* w_v   = (const float*)d_in[9];
    const float* b_v   = (const float*)d_in[10];
    const float* w_p   = (const float*)d_in[11];
    const float* b_p   = (const float*)d_in[12];
    const float* ln_g  = (const float*)d_in[13];
    const float* ln_b  = (const float*)d_in[14];
    const float* w_ih  = (const float*)d_in[15];
    const float* w_hh  = (const float*)d_in[16];
    const float* b_ih  = (const float*)d_in[17];
    const float* b_hh  = (const float*)d_in[18];
    const float* w_c1  = (const float*)d_in[19];
    const float* b_c1  = (const float*)d_in[20];
    const float* w_c2  = (const float*)d_in[21];
    const float* b_c2  = (const float*)d_in[22];
    float* out = (float*)d_out;

    float* h1   = sym(g_h1);
    float* hh   = sym(g_hh);
    float* q    = sym(g_q);
    float* k    = sym(g_k);
    float* v    = sym(g_v);
    float* sc   = sym(g_sc);
    float* o    = sym(g_o);
    float* y    = sym(g_y);
    float* gx   = sym(g_gx);
    float* lstm = sym(g_lstm);
    float* hbuf = sym(g_hbuf);
    float* a1   = sym(g_a1);
    float* a2   = sym(g_a2);
    float* wc1t = sym(g_wc1t);

    dim3 blk(128);

    // in_pro: 1x1 -> leaky -> 1x1
    gemm_tf32<1,1,1><<<dim3(4,64,1), blk>>>(x, w_in1, b_in1, h1,
        BT_, E_, E_, E_, E_, E_, 1, 0,0,0,0,0,0);
    gemm_tf32<0,1,1><<<dim3(4,64,1), blk>>>(h1, w_in2, b_in2, hh,
        BT_, E_, E_, E_, E_, E_, 1, 0,0,0,0,0,0);

    // QKV
    gemm_tf32<0,1,1><<<dim3(8,64,1), blk>>>(hh, w_q, b_q, q,
        BT_, NH_*QD_, E_, E_, E_, NH_*QD_, 1, 0,0,0,0,0,0);
    gemm_tf32<0,1,1><<<dim3(8,64,1), blk>>>(hh, w_k, b_k, k,
        BT_, NH_*QD_, E_, E_, E_, NH_*QD_, 1, 0,0,0,0,0,0);
    gemm_tf32<0,1,1><<<dim3(16,64,1), blk>>>(hh, w_v, b_v, v,
        BT_, NH_*VD_, E_, E_, E_, NH_*VD_, 1, 0,0,0,0,0,0);

    // scores = q @ k^T per (b, head)
    gemm_tf32<0,1,0><<<dim3(8,8,B_*NH_), blk>>>(q, k, nullptr, sc,
        T_, T_, QD_, NH_*QD_, NH_*QD_, T_, NH_,
        (long)T_*NH_*QD_, (long)QD_, (long)T_*NH_*QD_, (long)QD_,
        (long)NH_*T_*T_, (long)T_*T_);

    softmax_kernel<<<B_*NH_*T_, 256>>>(sc);

    // o = attn @ v per (b, head)
    gemm_tf32<0,0,0><<<dim3(4,8,B_*NH_), blk>>>(sc, v, nullptr, o,
        T_, VD_, T_, T_, NH_*VD_, NH_*VD_, NH_,
        (long)NH_*T_*T_, (long)T_*T_, (long)T_*NH_*VD_, (long)VD_,
        (long)T_*NH_*VD_, (long)VD_);

    // out projection + layernorm
    gemm_tf32<0,1,1><<<dim3(4,64,1), blk>>>(o, w_p, b_p, y,
        BT_, E_, NH_*VD_, NH_*VD_, NH_*VD_, E_, 1, 0,0,0,0,0,0);
    layernorm_kernel<<<BT_, 128>>>(y, ln_g, ln_b, y);

    // LSTM input GEMM: gx = y @ w_ih^T + b_ih
    gemm_tf32<0,1,1><<<dim3(32,64,1), blk>>>(y, w_ih, b_ih, gx,
        BT_, G4_, E_, E_, E_, G4_, 1, 0,0,0,0,0,0);

    reset_kernel<<<64, 256>>>();
    lstm_kernel<<<LSTM_NB, 256>>>(gx, w_hh, b_hh, hbuf, lstm);

    // conv pooling
    repack_wc1<<<(C1_*H_*3 + 255)/256, 256>>>(w_c1, wc1t);
    conv1_kernel<<<dim3(4,8,B_), 256>>>(lstm, wc1t, b_c1, a1);
    conv2_kernel<<<dim3(4,B_), 256>>>(a1, w_c2, b_c2, a2);
    softmax_kernel<<<B_*C2_, 256>>>(a2);

    // feat = a2 @ lstm_out : [2,1024]@[1024,1024] per batch -> out [8,2048]
    gemm_kernel<0,0,0><<<dim3(16,1,B_), 256>>>(a2, lstm, nullptr, out,
        C2_, H_, T_, T_, H_, H_, 1,
        (long)C2_*T_, 0, (long)T_*H_, 0, (long)C2_*H_, 0);
}